// round 1
// baseline (speedup 1.0000x reference)
#include <cuda_runtime.h>

#define SEQ 2048
#define DMODEL 1024
#define NH 16
#define HD 64
#define TILE_T 16
#define NANCH 3

// ---------------- scratch (static device allocations; no cudaMalloc) ----------
__device__ float g_lin[3][SEQ * DMODEL];   // q/k/v linear outputs [S, H*D]
__device__ float g_qh[NH * SEQ * HD];      // [H, S, D] after RoPE
__device__ float g_kh[NH * SEQ * HD];
__device__ float g_vh[NH * SEQ * HD];
__device__ float g_att[SEQ * DMODEL];      // attention output [S, H*D]

// ---------------- classic 128x128x8 SGEMM, 256 threads, 8x8 microtile --------
// gridDim.z selects (B,C) pair -> fuses Q,K,V projections into one launch.
__global__ void __launch_bounds__(256) sgemm3(
    const float* __restrict__ A,
    const float* __restrict__ B0, const float* __restrict__ B1, const float* __restrict__ B2,
    float* __restrict__ C0, float* __restrict__ C1, float* __restrict__ C2,
    int M, int N, int K)
{
    const float* B = (blockIdx.z == 0) ? B0 : (blockIdx.z == 1 ? B1 : B2);
    float*       C = (blockIdx.z == 0) ? C0 : (blockIdx.z == 1 ? C1 : C2);

    __shared__ float As[8][128];
    __shared__ float Bs[8][128];

    const int tid  = threadIdx.x;
    const int aRow = tid >> 1;            // 0..127
    const int aCol = (tid & 1) * 4;       // 0 or 4
    const int bRow = tid >> 5;            // 0..7
    const int bCol = (tid & 31) * 4;      // 0..124

    const int blockRow = blockIdx.y * 128;
    const int blockCol = blockIdx.x * 128;

    A += (size_t)blockRow * K;
    B += blockCol;
    C += (size_t)blockRow * N + blockCol;

    const int ty = (tid >> 4) * 8;        // 0..120
    const int tx = (tid & 15) * 8;        // 0..120

    float acc[8][8] = {};

    for (int k0 = 0; k0 < K; k0 += 8) {
        float4 av = *(const float4*)(A + (size_t)aRow * K + k0 + aCol);
        As[aCol + 0][aRow] = av.x;
        As[aCol + 1][aRow] = av.y;
        As[aCol + 2][aRow] = av.z;
        As[aCol + 3][aRow] = av.w;
        float4 bv = *(const float4*)(B + (size_t)(k0 + bRow) * N + bCol);
        *(float4*)&Bs[bRow][bCol] = bv;
        __syncthreads();

        #pragma unroll
        for (int kk = 0; kk < 8; kk++) {
            float4 a0 = *(const float4*)&As[kk][ty];
            float4 a1 = *(const float4*)&As[kk][ty + 4];
            float4 b0 = *(const float4*)&Bs[kk][tx];
            float4 b1 = *(const float4*)&Bs[kk][tx + 4];
            float a[8] = {a0.x, a0.y, a0.z, a0.w, a1.x, a1.y, a1.z, a1.w};
            float b[8] = {b0.x, b0.y, b0.z, b0.w, b1.x, b1.y, b1.z, b1.w};
            #pragma unroll
            for (int i = 0; i < 8; i++)
                #pragma unroll
                for (int j = 0; j < 8; j++)
                    acc[i][j] = fmaf(a[i], b[j], acc[i][j]);
        }
        __syncthreads();
    }

    #pragma unroll
    for (int i = 0; i < 8; i++) {
        float* crow = C + (size_t)(ty + i) * N + tx;
        *(float4*)(crow)     = make_float4(acc[i][0], acc[i][1], acc[i][2], acc[i][3]);
        *(float4*)(crow + 4) = make_float4(acc[i][4], acc[i][5], acc[i][6], acc[i][7]);
    }
}

// ---------------- RoPE + [S,H*D] -> [H,S,D] relayout -------------------------
__global__ void rope_reshape(const float* __restrict__ cosT,
                             const float* __restrict__ sinT)
{
    const int s = blockIdx.x;
    const int h = blockIdx.y;
    const int d = threadIdx.x;           // 0..63

    const int src = s * DMODEL + h * HD + d;
    const int dst = (h * SEQ + s) * HD + d;

    const float qv = g_lin[0][src];
    const float kv = g_lin[1][src];
    float qo, ko;
    if (d < 32) {
        const float c  = cosT[s * 32 + d];
        const float sn = sinT[s * 32 + d];
        qo = qv * c - g_lin[0][src + 32] * sn;
        ko = kv * c - g_lin[1][src + 32] * sn;
    } else {
        const float c  = cosT[s * 32 + d - 32];
        const float sn = sinT[s * 32 + d - 32];
        qo = qv * c + g_lin[0][src - 32] * sn;
        ko = kv * c + g_lin[1][src - 32] * sn;
    }
    g_qh[dst] = qo;
    g_kh[dst] = ko;
    g_vh[dst] = g_lin[2][src];
}

// ---------------- sparse attention: 1 block (64 thr) per (h, q) --------------
__global__ void __launch_bounds__(64) attn(const int* __restrict__ anchors)
{
    const int s = blockIdx.x;
    const int h = blockIdx.y;
    const int j = threadIdx.x;           // key slot AND output dim

    __shared__ float sq[64];
    __shared__ float sw[64];
    __shared__ int   sidx[64];
    __shared__ float wred[2][2];

    sq[j] = g_qh[(h * SEQ + s) * HD + j];

    const int slot = j >> 4;
    const int t    = j & 15;
    const int tile = (slot < NANCH) ? anchors[(h * SEQ + s) * NANCH + slot] : (s >> 4);
    int kidx = tile * TILE_T + t;
    kidx = min(max(kidx, 0), SEQ - 1);
    const bool masked = kidx > s;
    __syncthreads();

    float logit = -1e30f;
    if (!masked) {
        const float* krow = &g_kh[(h * SEQ + kidx) * HD];
        float acc = 0.f;
        #pragma unroll
        for (int dd = 0; dd < 64; dd++)
            acc = fmaf(sq[dd], krow[dd], acc);
        logit = acc * 0.125f;            // 1/sqrt(64)
    }

    const int wid  = j >> 5;
    const int lane = j & 31;

    // max-reduce over 64
    float m = logit;
    #pragma unroll
    for (int off = 16; off; off >>= 1)
        m = fmaxf(m, __shfl_xor_sync(0xffffffffu, m, off));
    if (lane == 0) wred[0][wid] = m;
    __syncthreads();
    m = fmaxf(wred[0][0], wred[0][1]);

    const float e = masked ? 0.f : __expf(logit - m);

    // sum-reduce over 64
    float ssum = e;
    #pragma unroll
    for (int off = 16; off; off >>= 1)
        ssum += __shfl_xor_sync(0xffffffffu, ssum, off);
    if (lane == 0) wred[1][wid] = ssum;
    __syncthreads();
    ssum = wred[1][0] + wred[1][1];      // >0: local tile always contains self

    sw[j]   = e / ssum;
    sidx[j] = kidx;
    __syncthreads();

    // output: thread j owns dim j; coalesced v reads across threads
    float acc = 0.f;
    #pragma unroll
    for (int jj = 0; jj < 64; jj++)
        acc = fmaf(sw[jj], g_vh[(h * SEQ + sidx[jj]) * HD + j], acc);

    g_att[s * DMODEL + h * HD + j] = acc;
}

// ---------------- launch ------------------------------------------------------
extern "C" void kernel_launch(void* const* d_in, const int* in_sizes, int n_in,
                              void* d_out, int out_size)
{
    const float* x       = (const float*)d_in[0];
    const float* Wq      = (const float*)d_in[1];
    const float* Wk      = (const float*)d_in[2];
    const float* Wv      = (const float*)d_in[3];
    const float* Wo      = (const float*)d_in[4];
    const float* cosT    = (const float*)d_in[5];
    const float* sinT    = (const float*)d_in[6];
    const int*   anchors = (const int*)d_in[7];
    float* out = (float*)d_out;

    float* lin = nullptr;
    float* att = nullptr;
    cudaGetSymbolAddress((void**)&lin, g_lin);
    cudaGetSymbolAddress((void**)&att, g_att);

    // QKV projections: one launch, z selects weight/output
    dim3 g1(DMODEL / 128, SEQ / 128, 3);
    sgemm3<<<g1, 256>>>(x, Wq, Wk, Wv,
                        lin, lin + (size_t)SEQ * DMODEL, lin + 2 * (size_t)SEQ * DMODEL,
                        SEQ, DMODEL, DMODEL);

    rope_reshape<<<dim3(SEQ, NH), 64>>>(cosT, sinT);

    attn<<<dim3(SEQ, NH), 64>>>(anchors);

    // output projection
    dim3 g2(DMODEL / 128, SEQ / 128, 1);
    sgemm3<<<g2, 256>>>(att, Wo, Wo, Wo, out, out, out, SEQ, DMODEL, DMODEL);
}

// round 3
// speedup vs baseline: 1.7249x; 1.7249x over previous
#include <cuda_runtime.h>
#include <cuda_bf16.h>
#include <cstdint>

#define SEQ 2048
#define DM 1024
#define NH 16
#define HD 64
#define NANCH 3

// ---------------- scratch ------------------------------------------------------
__device__ float g_lin[SEQ * 3072];                 // fused q|k|v rows [S, 3072]
__device__ float g_qh[NH * SEQ * HD];
__device__ float g_kh[NH * SEQ * HD];
__device__ float g_vh[NH * SEQ * HD];
__device__ __nv_bfloat16 g_xhi[SEQ * DM], g_xlo[SEQ * DM];        // x split
__device__ __nv_bfloat16 g_wthi[3072 * DM], g_wtlo[3072 * DM];    // [n,k] Wq|Wk|Wv^T split
__device__ __nv_bfloat16 g_wothi[DM * DM], g_wotlo[DM * DM];      // [n,k] Wo^T split
__device__ __nv_bfloat16 g_athi[SEQ * DM], g_atlo[SEQ * DM];      // attn out split

// ---------------- PTX helpers --------------------------------------------------
__device__ __forceinline__ uint32_t smem_u32(const void* p) {
    uint32_t a;
    asm("{ .reg .u64 t; cvta.to.shared.u64 t, %1; cvt.u32.u64 %0, t; }" : "=r"(a) : "l"(p));
    return a;
}
__device__ __forceinline__ void cp16(uint32_t s, const void* g) {
    asm volatile("cp.async.cg.shared.global [%0], [%1], 16;" :: "r"(s), "l"(g));
}
#define CP_COMMIT() asm volatile("cp.async.commit_group;" ::: "memory")
#define CP_WAIT1()  asm volatile("cp.async.wait_group 1;" ::: "memory")

__device__ __forceinline__ void ldsm_x4(uint32_t& r0, uint32_t& r1, uint32_t& r2,
                                        uint32_t& r3, uint32_t a) {
    asm volatile("ldmatrix.sync.aligned.m8n8.x4.shared.b16 {%0,%1,%2,%3}, [%4];"
                 : "=r"(r0), "=r"(r1), "=r"(r2), "=r"(r3) : "r"(a));
}
__device__ __forceinline__ void mma16816(float* d, const uint32_t* a, const uint32_t* b) {
    asm volatile(
        "mma.sync.aligned.m16n8k16.row.col.f32.bf16.bf16.f32 "
        "{%0,%1,%2,%3}, {%4,%5,%6,%7}, {%8,%9}, {%0,%1,%2,%3};"
        : "+f"(d[0]), "+f"(d[1]), "+f"(d[2]), "+f"(d[3])
        : "r"(a[0]), "r"(a[1]), "r"(a[2]), "r"(a[3]), "r"(b[0]), "r"(b[1]));
}

// ---------------- split/transpose prep -----------------------------------------
__global__ void split_x(const float* __restrict__ x) {
    int i = blockIdx.x * 256 + threadIdx.x;
    float v = x[i];
    __nv_bfloat16 hi = __float2bfloat16(v);
    g_xhi[i] = hi;
    g_xlo[i] = __float2bfloat16(v - __bfloat162float(hi));
}

// W [k][n] -> Wt [n][k] hi/lo. z: 0..2 -> Wq/Wk/Wv, 3 -> Wo
__global__ void transpose_split(const float* __restrict__ Wq, const float* __restrict__ Wk,
                                const float* __restrict__ Wv, const float* __restrict__ Wo) {
    __shared__ float tile[32][33];
    int z = blockIdx.z;
    const float* W = (z == 0) ? Wq : (z == 1) ? Wk : (z == 2) ? Wv : Wo;
    __nv_bfloat16* ohi = (z < 3) ? (g_wthi + (size_t)z * DM * DM) : g_wothi;
    __nv_bfloat16* olo = (z < 3) ? (g_wtlo + (size_t)z * DM * DM) : g_wotlo;
    int k0 = blockIdx.y * 32, n0 = blockIdx.x * 32;
    int tx = threadIdx.x, ty = threadIdx.y;
    tile[ty][tx] = W[(size_t)(k0 + ty) * DM + n0 + tx];
    __syncthreads();
    float v = tile[tx][ty];
    __nv_bfloat16 hi = __float2bfloat16(v);
    size_t o = (size_t)(n0 + ty) * DM + k0 + tx;
    ohi[o] = hi;
    olo[o] = __float2bfloat16(v - __bfloat162float(hi));
}

// ---------------- mma.sync bf16x3 GEMM: C[M,N] = A[M,K] @ B[N,K]^T --------------
// 128x128x32 CTA tile, 8 warps (4m x 2n), 3-stage cp.async pipeline.
#define BK 32
#define NSTAGE 3
#define STG 32768
#define OFF_AHI 0
#define OFF_ALO 8192
#define OFF_BHI 16384
#define OFF_BLO 24576

// smem row: 32 bf16 = 64B = 4 x 16B segs; swizzle seg' = seg ^ (row & 3)
__device__ __forceinline__ uint32_t swz(uint32_t row, uint32_t seg) {
    return row * 64 + ((seg ^ (row & 3)) << 4);
}

__device__ __forceinline__ void load_chunk(
    uint32_t stage, int tid, int c, int m0, int n0, int K,
    const __nv_bfloat16* Ahi, const __nv_bfloat16* Alo,
    const __nv_bfloat16* Bhi, const __nv_bfloat16* Blo)
{
    const __nv_bfloat16* srcs[4] = {Ahi, Alo, Bhi, Blo};
    const uint32_t offs[4] = {OFF_AHI, OFF_ALO, OFF_BHI, OFF_BLO};
    #pragma unroll
    for (int mtx = 0; mtx < 4; mtx++) {
        const int r0 = (mtx < 2) ? m0 : n0;
        const __nv_bfloat16* src = srcs[mtx];
        #pragma unroll
        for (int i = 0; i < 2; i++) {
            int lin = i * 256 + tid;                  // 512 x 16B per matrix
            int row = lin >> 2, seg = lin & 3;
            const void* g = src + (size_t)(r0 + row) * K + c * BK + seg * 8;
            cp16(stage + offs[mtx] + swz(row, seg), g);
        }
    }
}

__global__ void __launch_bounds__(256) gemm_mma(
    const __nv_bfloat16* __restrict__ Ahi, const __nv_bfloat16* __restrict__ Alo,
    const __nv_bfloat16* __restrict__ Bhi, const __nv_bfloat16* __restrict__ Blo,
    float* __restrict__ C, int Nstride, int K)
{
    extern __shared__ __align__(1024) char dsm[];
    const uint32_t tiles = smem_u32(dsm);

    const int tid = threadIdx.x;
    const int m0 = blockIdx.y * 128, n0 = blockIdx.x * 128;
    const int nCh = K / BK;

    const int w = tid >> 5, lane = tid & 31;
    const int wm = (w & 3) * 32;       // warp row offset in tile
    const int wn = (w >> 2) * 64;      // warp col offset in tile

    float acc[2][8][4];
    #pragma unroll
    for (int i = 0; i < 2; i++)
        #pragma unroll
        for (int j = 0; j < 8; j++)
            #pragma unroll
            for (int e = 0; e < 4; e++) acc[i][j][e] = 0.f;

    load_chunk(tiles, tid, 0, m0, n0, K, Ahi, Alo, Bhi, Blo); CP_COMMIT();
    load_chunk(tiles + STG, tid, 1, m0, n0, K, Ahi, Alo, Bhi, Blo); CP_COMMIT();

    // ldmatrix lane roles
    const int aRowL = lane & 15;       // + mt*16 (+wm)
    const int aSegL = lane >> 4;       // + k16*2
    const int bRowL = ((lane >> 4) & 1) * 8 + (lane & 7);  // + np*16 (+wn)
    const int bSegL = (lane >> 3) & 1;                     // + k16*2

    for (int c = 0; c < nCh; c++) {
        const uint32_t buf = tiles + (c % NSTAGE) * STG;
        CP_WAIT1();
        __syncthreads();
        if (c + 2 < nCh)
            load_chunk(tiles + ((c + 2) % NSTAGE) * STG, tid, c + 2, m0, n0, K,
                       Ahi, Alo, Bhi, Blo);
        CP_COMMIT();

        #pragma unroll
        for (int k16 = 0; k16 < 2; k16++) {
            uint32_t aH[2][4], aL[2][4], bH[4][4], bL[4][4];
            #pragma unroll
            for (int mt = 0; mt < 2; mt++) {
                uint32_t row = wm + mt * 16 + aRowL;
                uint32_t off = swz(row, k16 * 2 + aSegL);
                ldsm_x4(aH[mt][0], aH[mt][1], aH[mt][2], aH[mt][3], buf + OFF_AHI + off);
                ldsm_x4(aL[mt][0], aL[mt][1], aL[mt][2], aL[mt][3], buf + OFF_ALO + off);
            }
            #pragma unroll
            for (int np = 0; np < 4; np++) {
                uint32_t row = wn + np * 16 + bRowL;
                uint32_t off = swz(row, k16 * 2 + bSegL);
                ldsm_x4(bH[np][0], bH[np][1], bH[np][2], bH[np][3], buf + OFF_BHI + off);
                ldsm_x4(bL[np][0], bL[np][1], bL[np][2], bL[np][3], buf + OFF_BLO + off);
            }
            #pragma unroll
            for (int mt = 0; mt < 2; mt++)
                #pragma unroll
                for (int np = 0; np < 4; np++)
                    #pragma unroll
                    for (int h = 0; h < 2; h++) {
                        float* d = acc[mt][np * 2 + h];
                        mma16816(d, aH[mt], &bH[np][h * 2]);
                        mma16816(d, aH[mt], &bL[np][h * 2]);
                        mma16816(d, aL[mt], &bH[np][h * 2]);
                    }
        }
        __syncthreads();
    }

    // epilogue
    const int erow = lane >> 2, ecol = (lane & 3) * 2;
    #pragma unroll
    for (int mt = 0; mt < 2; mt++)
        #pragma unroll
        for (int nt = 0; nt < 8; nt++) {
            const float* d = acc[mt][nt];
            size_t r = (size_t)(m0 + wm + mt * 16 + erow);
            size_t col = n0 + wn + nt * 8 + ecol;
            *(float2*)&C[r * Nstride + col]       = make_float2(d[0], d[1]);
            *(float2*)&C[(r + 8) * Nstride + col] = make_float2(d[2], d[3]);
        }
}

// ---------------- RoPE + relayout ----------------------------------------------
__global__ void rope_reshape(const float* __restrict__ cosT, const float* __restrict__ sinT) {
    const int s = blockIdx.x, h = blockIdx.y, d = threadIdx.x;
    const int base = s * 3072 + h * HD;
    const int dst = (h * SEQ + s) * HD + d;
    const float qv = g_lin[base + d];
    const float kv = g_lin[base + 1024 + d];
    float qo, ko;
    if (d < 32) {
        const float c = cosT[s * 32 + d], sn = sinT[s * 32 + d];
        qo = qv * c - g_lin[base + d + 32] * sn;
        ko = kv * c - g_lin[base + 1024 + d + 32] * sn;
    } else {
        const float c = cosT[s * 32 + d - 32], sn = sinT[s * 32 + d - 32];
        qo = qv * c + g_lin[base + d - 32] * sn;
        ko = kv * c + g_lin[base + 1024 + d - 32] * sn;
    }
    g_qh[dst] = qo;
    g_kh[dst] = ko;
    g_vh[dst] = g_lin[base + 2048 + d];
}

// ---------------- sparse attention ---------------------------------------------
__global__ void __launch_bounds__(64) attn(const int* __restrict__ anchors) {
    const int s = blockIdx.x, h = blockIdx.y, j = threadIdx.x;

    __shared__ float sq[64];
    __shared__ float sw[64];
    __shared__ int sidx[64];
    __shared__ float wred[2][2];

    sq[j] = g_qh[(h * SEQ + s) * HD + j];

    const int slot = j >> 4, t = j & 15;
    const int tile = (slot < NANCH) ? anchors[(h * SEQ + s) * NANCH + slot] : (s >> 4);
    int kidx = min(max(tile * 16 + t, 0), SEQ - 1);
    const bool masked = kidx > s;
    __syncthreads();

    float logit = -1e30f;
    if (!masked) {
        const float* krow = &g_kh[(h * SEQ + kidx) * HD];
        float acc = 0.f;
        #pragma unroll
        for (int dd = 0; dd < 64; dd++) acc = fmaf(sq[dd], krow[dd], acc);
        logit = acc * 0.125f;
    }

    const int wid = j >> 5, lane = j & 31;
    float m = logit;
    #pragma unroll
    for (int off = 16; off; off >>= 1) m = fmaxf(m, __shfl_xor_sync(~0u, m, off));
    if (lane == 0) wred[0][wid] = m;
    __syncthreads();
    m = fmaxf(wred[0][0], wred[0][1]);

    const float e = masked ? 0.f : __expf(logit - m);
    float ssum = e;
    #pragma unroll
    for (int off = 16; off; off >>= 1) ssum += __shfl_xor_sync(~0u, ssum, off);
    if (lane == 0) wred[1][wid] = ssum;
    __syncthreads();
    ssum = wred[1][0] + wred[1][1];

    sw[j] = e / ssum;
    sidx[j] = kidx;
    __syncthreads();

    float acc = 0.f;
    #pragma unroll
    for (int jj = 0; jj < 64; jj++)
        acc = fmaf(sw[jj], g_vh[(h * SEQ + sidx[jj]) * HD + j], acc);

    __nv_bfloat16 hi = __float2bfloat16(acc);
    const int o = s * DM + h * HD + j;
    g_athi[o] = hi;
    g_atlo[o] = __float2bfloat16(acc - __bfloat162float(hi));
}

// ---------------- launch ---------------------------------------------------------
extern "C" void kernel_launch(void* const* d_in, const int* in_sizes, int n_in,
                              void* d_out, int out_size)
{
    const float* x    = (const float*)d_in[0];
    const float* Wq   = (const float*)d_in[1];
    const float* Wk   = (const float*)d_in[2];
    const float* Wv   = (const float*)d_in[3];
    const float* Wo   = (const float*)d_in[4];
    const float* cosT = (const float*)d_in[5];
    const float* sinT = (const float*)d_in[6];
    const int* anchors = (const int*)d_in[7];
    float* out = (float*)d_out;

    const int SMEM_SZ = NSTAGE * STG;    // 96 KB
    cudaFuncSetAttribute(gemm_mma, cudaFuncAttributeMaxDynamicSharedMemorySize, SMEM_SZ);

    float* lin = nullptr;
    __nv_bfloat16 *xhi = nullptr, *xlo = nullptr, *wthi = nullptr, *wtlo = nullptr;
    __nv_bfloat16 *wothi = nullptr, *wotlo = nullptr, *athi = nullptr, *atlo = nullptr;
    cudaGetSymbolAddress((void**)&lin, g_lin);
    cudaGetSymbolAddress((void**)&xhi, g_xhi);
    cudaGetSymbolAddress((void**)&xlo, g_xlo);
    cudaGetSymbolAddress((void**)&wthi, g_wthi);
    cudaGetSymbolAddress((void**)&wtlo, g_wtlo);
    cudaGetSymbolAddress((void**)&wothi, g_wothi);
    cudaGetSymbolAddress((void**)&wotlo, g_wotlo);
    cudaGetSymbolAddress((void**)&athi, g_athi);
    cudaGetSymbolAddress((void**)&atlo, g_atlo);

    split_x<<<(SEQ * DM) / 256, 256>>>(x);
    transpose_split<<<dim3(32, 32, 4), dim3(32, 32)>>>(Wq, Wk, Wv, Wo);

    // qkv = x @ [Wq|Wk|Wv] -> g_lin [2048, 3072]
    gemm_mma<<<dim3(24, 16), 256, SMEM_SZ>>>(xhi, xlo, wthi, wtlo, lin, 3072, DM);

    rope_reshape<<<dim3(SEQ, NH), 64>>>(cosT, sinT);
    attn<<<dim3(SEQ, NH), 64>>>(anchors);

    // out = att @ Wo
    gemm_mma<<<dim3(8, 16), 256, SMEM_SZ>>>(athi, atlo, wothi, wotlo, out, DM, DM);
}

// round 4
// speedup vs baseline: 2.7645x; 1.6027x over previous
#include <cuda_runtime.h>
#include <cuda_bf16.h>
#include <cstdint>

#define SEQ 2048
#define DM 1024
#define NH 16
#define HD 64
#define NANCH 3
#define QPB 4

// ---------------- scratch ------------------------------------------------------
__device__ float g_lin[SEQ * 3072];                 // fused q|k|v rows [S, 3072]
__device__ float g_kh[NH * SEQ * HD];               // K after RoPE, [H,S,D]
__device__ __nv_bfloat16 g_xhi[SEQ * DM], g_xlo[SEQ * DM];        // x split
__device__ __nv_bfloat16 g_wthi[3072 * DM], g_wtlo[3072 * DM];    // [n,k] Wq|Wk|Wv^T split
__device__ __nv_bfloat16 g_wothi[DM * DM], g_wotlo[DM * DM];      // [n,k] Wo^T split
__device__ __nv_bfloat16 g_athi[SEQ * DM], g_atlo[SEQ * DM];      // attn out split

// ---------------- PTX helpers --------------------------------------------------
__device__ __forceinline__ uint32_t smem_u32(const void* p) {
    uint32_t a;
    asm("{ .reg .u64 t; cvta.to.shared.u64 t, %1; cvt.u32.u64 %0, t; }" : "=r"(a) : "l"(p));
    return a;
}
__device__ __forceinline__ void cp16(uint32_t s, const void* g) {
    asm volatile("cp.async.cg.shared.global [%0], [%1], 16;" :: "r"(s), "l"(g));
}
#define CP_COMMIT() asm volatile("cp.async.commit_group;" ::: "memory")
#define CP_WAIT1()  asm volatile("cp.async.wait_group 1;" ::: "memory")

__device__ __forceinline__ void ldsm_x4(uint32_t& r0, uint32_t& r1, uint32_t& r2,
                                        uint32_t& r3, uint32_t a) {
    asm volatile("ldmatrix.sync.aligned.m8n8.x4.shared.b16 {%0,%1,%2,%3}, [%4];"
                 : "=r"(r0), "=r"(r1), "=r"(r2), "=r"(r3) : "r"(a));
}
__device__ __forceinline__ void mma16816(float* d, const uint32_t* a, const uint32_t* b) {
    asm volatile(
        "mma.sync.aligned.m16n8k16.row.col.f32.bf16.bf16.f32 "
        "{%0,%1,%2,%3}, {%4,%5,%6,%7}, {%8,%9}, {%0,%1,%2,%3};"
        : "+f"(d[0]), "+f"(d[1]), "+f"(d[2]), "+f"(d[3])
        : "r"(a[0]), "r"(a[1]), "r"(a[2]), "r"(a[3]), "r"(b[0]), "r"(b[1]));
}

// ---------------- split/transpose prep -----------------------------------------
__global__ void split_x(const float* __restrict__ x) {
    int i = blockIdx.x * 256 + threadIdx.x;
    float v = x[i];
    __nv_bfloat16 hi = __float2bfloat16(v);
    g_xhi[i] = hi;
    g_xlo[i] = __float2bfloat16(v - __bfloat162float(hi));
}

// W [k][n] -> Wt [n][k] hi/lo. z: 0..2 -> Wq/Wk/Wv, 3 -> Wo
__global__ void transpose_split(const float* __restrict__ Wq, const float* __restrict__ Wk,
                                const float* __restrict__ Wv, const float* __restrict__ Wo) {
    __shared__ float tile[32][33];
    int z = blockIdx.z;
    const float* W = (z == 0) ? Wq : (z == 1) ? Wk : (z == 2) ? Wv : Wo;
    __nv_bfloat16* ohi = (z < 3) ? (g_wthi + (size_t)z * DM * DM) : g_wothi;
    __nv_bfloat16* olo = (z < 3) ? (g_wtlo + (size_t)z * DM * DM) : g_wotlo;
    int k0 = blockIdx.y * 32, n0 = blockIdx.x * 32;
    int tx = threadIdx.x, ty = threadIdx.y;
    tile[ty][tx] = W[(size_t)(k0 + ty) * DM + n0 + tx];
    __syncthreads();
    float v = tile[tx][ty];
    __nv_bfloat16 hi = __float2bfloat16(v);
    size_t o = (size_t)(n0 + ty) * DM + k0 + tx;
    ohi[o] = hi;
    olo[o] = __float2bfloat16(v - __bfloat162float(hi));
}

// ---------------- mma.sync bf16x3 GEMM: C[M,N] = A[M,K] @ B[N,K]^T --------------
#define BK 32
#define NSTAGE 3
#define STG 32768
#define OFF_AHI 0
#define OFF_ALO 8192
#define OFF_BHI 16384
#define OFF_BLO 24576

__device__ __forceinline__ uint32_t swz(uint32_t row, uint32_t seg) {
    return row * 64 + ((seg ^ (row & 3)) << 4);
}

__device__ __forceinline__ void load_chunk(
    uint32_t stage, int tid, int c, int m0, int n0, int K,
    const __nv_bfloat16* Ahi, const __nv_bfloat16* Alo,
    const __nv_bfloat16* Bhi, const __nv_bfloat16* Blo)
{
    const __nv_bfloat16* srcs[4] = {Ahi, Alo, Bhi, Blo};
    const uint32_t offs[4] = {OFF_AHI, OFF_ALO, OFF_BHI, OFF_BLO};
    #pragma unroll
    for (int mtx = 0; mtx < 4; mtx++) {
        const int r0 = (mtx < 2) ? m0 : n0;
        const __nv_bfloat16* src = srcs[mtx];
        #pragma unroll
        for (int i = 0; i < 2; i++) {
            int lin = i * 256 + tid;
            int row = lin >> 2, seg = lin & 3;
            const void* g = src + (size_t)(r0 + row) * K + c * BK + seg * 8;
            cp16(stage + offs[mtx] + swz(row, seg), g);
        }
    }
}

__global__ void __launch_bounds__(256) gemm_mma(
    const __nv_bfloat16* __restrict__ Ahi, const __nv_bfloat16* __restrict__ Alo,
    const __nv_bfloat16* __restrict__ Bhi, const __nv_bfloat16* __restrict__ Blo,
    float* __restrict__ C, int Nstride, int K)
{
    extern __shared__ __align__(1024) char dsm[];
    const uint32_t tiles = smem_u32(dsm);

    const int tid = threadIdx.x;
    const int m0 = blockIdx.y * 128, n0 = blockIdx.x * 128;
    const int nCh = K / BK;

    const int w = tid >> 5, lane = tid & 31;
    const int wm = (w & 3) * 32;
    const int wn = (w >> 2) * 64;

    float acc[2][8][4];
    #pragma unroll
    for (int i = 0; i < 2; i++)
        #pragma unroll
        for (int j = 0; j < 8; j++)
            #pragma unroll
            for (int e = 0; e < 4; e++) acc[i][j][e] = 0.f;

    load_chunk(tiles, tid, 0, m0, n0, K, Ahi, Alo, Bhi, Blo); CP_COMMIT();
    load_chunk(tiles + STG, tid, 1, m0, n0, K, Ahi, Alo, Bhi, Blo); CP_COMMIT();

    const int aRowL = lane & 15;
    const int aSegL = lane >> 4;
    const int bRowL = ((lane >> 4) & 1) * 8 + (lane & 7);
    const int bSegL = (lane >> 3) & 1;

    for (int c = 0; c < nCh; c++) {
        const uint32_t buf = tiles + (c % NSTAGE) * STG;
        CP_WAIT1();
        __syncthreads();
        if (c + 2 < nCh)
            load_chunk(tiles + ((c + 2) % NSTAGE) * STG, tid, c + 2, m0, n0, K,
                       Ahi, Alo, Bhi, Blo);
        CP_COMMIT();

        #pragma unroll
        for (int k16 = 0; k16 < 2; k16++) {
            uint32_t aH[2][4], aL[2][4], bH[4][4], bL[4][4];
            #pragma unroll
            for (int mt = 0; mt < 2; mt++) {
                uint32_t row = wm + mt * 16 + aRowL;
                uint32_t off = swz(row, k16 * 2 + aSegL);
                ldsm_x4(aH[mt][0], aH[mt][1], aH[mt][2], aH[mt][3], buf + OFF_AHI + off);
                ldsm_x4(aL[mt][0], aL[mt][1], aL[mt][2], aL[mt][3], buf + OFF_ALO + off);
            }
            #pragma unroll
            for (int np = 0; np < 4; np++) {
                uint32_t row = wn + np * 16 + bRowL;
                uint32_t off = swz(row, k16 * 2 + bSegL);
                ldsm_x4(bH[np][0], bH[np][1], bH[np][2], bH[np][3], buf + OFF_BHI + off);
                ldsm_x4(bL[np][0], bL[np][1], bL[np][2], bL[np][3], buf + OFF_BLO + off);
            }
            #pragma unroll
            for (int mt = 0; mt < 2; mt++)
                #pragma unroll
                for (int np = 0; np < 4; np++)
                    #pragma unroll
                    for (int h = 0; h < 2; h++) {
                        float* d = acc[mt][np * 2 + h];
                        mma16816(d, aH[mt], &bH[np][h * 2]);
                        mma16816(d, aH[mt], &bL[np][h * 2]);
                        mma16816(d, aL[mt], &bH[np][h * 2]);
                    }
        }
        __syncthreads();
    }

    const int erow = lane >> 2, ecol = (lane & 3) * 2;
    #pragma unroll
    for (int mt = 0; mt < 2; mt++)
        #pragma unroll
        for (int nt = 0; nt < 8; nt++) {
            const float* d = acc[mt][nt];
            size_t r = (size_t)(m0 + wm + mt * 16 + erow);
            size_t col = n0 + wn + nt * 8 + ecol;
            *(float2*)&C[r * Nstride + col]       = make_float2(d[0], d[1]);
            *(float2*)&C[(r + 8) * Nstride + col] = make_float2(d[2], d[3]);
        }
}

// ---------------- RoPE for K only: [S,3072] -> [H,S,D] -------------------------
__global__ void rope_k(const float* __restrict__ cosT, const float* __restrict__ sinT) {
    const int idx = blockIdx.x * 256 + threadIdx.x;   // 0 .. 2048*16*32-1
    const int d = idx & 31;
    const int h = (idx >> 5) & 15;
    const int s = idx >> 9;
    const int base = s * 3072 + 1024 + h * HD;
    const float k0 = g_lin[base + d];
    const float k1 = g_lin[base + d + 32];
    const float c = cosT[s * 32 + d], sn = sinT[s * 32 + d];
    const int dst = (h * SEQ + s) * HD + d;
    g_kh[dst]      = k0 * c - k1 * sn;
    g_kh[dst + 32] = k1 * c + k0 * sn;
}

// ---------------- sparse attention: 4 queries / 256-thread block ----------------
__global__ void __launch_bounds__(256) attn(const int* __restrict__ anchors,
                                            const float* __restrict__ cosT,
                                            const float* __restrict__ sinT) {
    const int h = blockIdx.y;
    const int tid = threadIdx.x;
    const int ql = tid >> 6;                 // 0..3
    const int j = tid & 63;                  // key slot AND output dim
    const int s = blockIdx.x * QPB + ql;

    __shared__ float sqraw[QPB][64];
    __shared__ float4 sq4[QPB][16];
    __shared__ float swt[QPB][64];
    __shared__ int sidx[QPB][64];
    __shared__ float wred[QPB][2][2];

    sqraw[ql][j] = g_lin[s * 3072 + h * HD + j];

    const int slot = j >> 4, t = j & 15;
    const int tile = (slot < NANCH) ? anchors[(h * SEQ + s) * NANCH + slot] : (s >> 4);
    int kidx = min(max(tile * 16 + t, 0), SEQ - 1);
    const bool masked = kidx > s;
    sidx[ql][j] = kidx;
    __syncthreads();

    // RoPE on q (in smem)
    {
        const float c = cosT[s * 32 + (j & 31)], sn = sinT[s * 32 + (j & 31)];
        const float v = sqraw[ql][j];
        const float p = sqraw[ql][j ^ 32];
        ((float*)sq4[ql])[j] = (j < 32) ? (v * c - p * sn) : (v * c + p * sn);
    }
    __syncthreads();

    // logit: thread j vs gathered key row, float4 dot
    float logit = -1e30f;
    if (!masked) {
        const float4* kr = (const float4*)&g_kh[((size_t)h * SEQ + kidx) * HD];
        float acc = 0.f;
        #pragma unroll
        for (int dd = 0; dd < 16; dd++) {
            const float4 kv = kr[dd];
            const float4 qv = sq4[ql][dd];
            acc = fmaf(kv.x, qv.x, acc);
            acc = fmaf(kv.y, qv.y, acc);
            acc = fmaf(kv.z, qv.z, acc);
            acc = fmaf(kv.w, qv.w, acc);
        }
        logit = acc * 0.125f;
    }

    const int wq = (tid >> 5) & 1, lane = tid & 31;
    float m = logit;
    #pragma unroll
    for (int off = 16; off; off >>= 1) m = fmaxf(m, __shfl_xor_sync(~0u, m, off));
    if (lane == 0) wred[ql][0][wq] = m;
    __syncthreads();
    m = fmaxf(wred[ql][0][0], wred[ql][0][1]);

    const float e = masked ? 0.f : __expf(logit - m);
    float ssum = e;
    #pragma unroll
    for (int off = 16; off; off >>= 1) ssum += __shfl_xor_sync(~0u, ssum, off);
    if (lane == 0) wred[ql][1][wq] = ssum;
    __syncthreads();
    ssum = wred[ql][1][0] + wred[ql][1][1];   // >0: local tile contains self

    swt[ql][j] = e / ssum;
    __syncthreads();

    // output: thread j owns dim j; V read directly from g_lin (coalesced in j)
    const float* vbase = g_lin + 2048 + h * HD + j;
    float acc = 0.f;
    #pragma unroll 16
    for (int jj = 0; jj < 64; jj++)
        acc = fmaf(swt[ql][jj], vbase[(size_t)sidx[ql][jj] * 3072], acc);

    __nv_bfloat16 hi = __float2bfloat16(acc);
    const int o = s * DM + h * HD + j;
    g_athi[o] = hi;
    g_atlo[o] = __float2bfloat16(acc - __bfloat162float(hi));
}

// ---------------- launch ---------------------------------------------------------
extern "C" void kernel_launch(void* const* d_in, const int* in_sizes, int n_in,
                              void* d_out, int out_size)
{
    const float* x    = (const float*)d_in[0];
    const float* Wq   = (const float*)d_in[1];
    const float* Wk   = (const float*)d_in[2];
    const float* Wv   = (const float*)d_in[3];
    const float* Wo   = (const float*)d_in[4];
    const float* cosT = (const float*)d_in[5];
    const float* sinT = (const float*)d_in[6];
    const int* anchors = (const int*)d_in[7];
    float* out = (float*)d_out;

    const int SMEM_SZ = NSTAGE * STG;    // 96 KB
    cudaFuncSetAttribute(gemm_mma, cudaFuncAttributeMaxDynamicSharedMemorySize, SMEM_SZ);

    float* lin = nullptr;
    __nv_bfloat16 *xhi = nullptr, *xlo = nullptr, *wthi = nullptr, *wtlo = nullptr;
    __nv_bfloat16 *wothi = nullptr, *wotlo = nullptr, *athi = nullptr, *atlo = nullptr;
    cudaGetSymbolAddress((void**)&lin, g_lin);
    cudaGetSymbolAddress((void**)&xhi, g_xhi);
    cudaGetSymbolAddress((void**)&xlo, g_xlo);
    cudaGetSymbolAddress((void**)&wthi, g_wthi);
    cudaGetSymbolAddress((void**)&wtlo, g_wtlo);
    cudaGetSymbolAddress((void**)&wothi, g_wothi);
    cudaGetSymbolAddress((void**)&wotlo, g_wotlo);
    cudaGetSymbolAddress((void**)&athi, g_athi);
    cudaGetSymbolAddress((void**)&atlo, g_atlo);

    split_x<<<(SEQ * DM) / 256, 256>>>(x);
    transpose_split<<<dim3(32, 32, 4), dim3(32, 32)>>>(Wq, Wk, Wv, Wo);

    // qkv = x @ [Wq|Wk|Wv] -> g_lin [2048, 3072]
    gemm_mma<<<dim3(24, 16), 256, SMEM_SZ>>>(xhi, xlo, wthi, wtlo, lin, 3072, DM);

    rope_k<<<(SEQ * NH * 32) / 256, 256>>>(cosT, sinT);
    attn<<<dim3(SEQ / QPB, NH), 256>>>(anchors, cosT, sinT);

    // out = att @ Wo
    gemm_mma<<<dim3(8, 16), 256, SMEM_SZ>>>(athi, atlo, wothi, wotlo, out, DM, DM);
}

// round 5
// speedup vs baseline: 3.7026x; 1.3393x over previous
#include <cuda_runtime.h>
#include <cuda_bf16.h>
#include <cuda_fp16.h>
#include <cstdint>

#define SEQ 2048
#define DM 1024
#define NH 16
#define HD 64
#define NANCH 3
#define QPB 4

// ---------------- scratch ------------------------------------------------------
__device__ float g_lin[SEQ * 3072];                 // fused q|k|v rows [S, 3072]
__device__ float g_kh[NH * SEQ * HD];               // K after RoPE, [H,S,D]
__device__ __half g_xh[SEQ * DM];                   // x fp16
__device__ __half g_wth[3072 * DM];                 // [n,k] Wq|Wk|Wv^T fp16
__device__ __nv_bfloat16 g_wothi[DM * DM], g_wotlo[DM * DM];      // [n,k] Wo^T split
__device__ __nv_bfloat16 g_athi[SEQ * DM], g_atlo[SEQ * DM];      // attn out split

// ---------------- PTX helpers --------------------------------------------------
__device__ __forceinline__ uint32_t smem_u32(const void* p) {
    uint32_t a;
    asm("{ .reg .u64 t; cvta.to.shared.u64 t, %1; cvt.u32.u64 %0, t; }" : "=r"(a) : "l"(p));
    return a;
}
__device__ __forceinline__ void cp16(uint32_t s, const void* g) {
    asm volatile("cp.async.cg.shared.global [%0], [%1], 16;" :: "r"(s), "l"(g));
}
#define CP_COMMIT() asm volatile("cp.async.commit_group;" ::: "memory")
#define CP_WAIT1()  asm volatile("cp.async.wait_group 1;" ::: "memory")

__device__ __forceinline__ void ldsm_x4(uint32_t& r0, uint32_t& r1, uint32_t& r2,
                                        uint32_t& r3, uint32_t a) {
    asm volatile("ldmatrix.sync.aligned.m8n8.x4.shared.b16 {%0,%1,%2,%3}, [%4];"
                 : "=r"(r0), "=r"(r1), "=r"(r2), "=r"(r3) : "r"(a));
}
__device__ __forceinline__ void mma_bf16(float* d, const uint32_t* a, const uint32_t* b) {
    asm volatile(
        "mma.sync.aligned.m16n8k16.row.col.f32.bf16.bf16.f32 "
        "{%0,%1,%2,%3}, {%4,%5,%6,%7}, {%8,%9}, {%0,%1,%2,%3};"
        : "+f"(d[0]), "+f"(d[1]), "+f"(d[2]), "+f"(d[3])
        : "r"(a[0]), "r"(a[1]), "r"(a[2]), "r"(a[3]), "r"(b[0]), "r"(b[1]));
}
__device__ __forceinline__ void mma_f16(float* d, const uint32_t* a, const uint32_t* b) {
    asm volatile(
        "mma.sync.aligned.m16n8k16.row.col.f32.f16.f16.f32 "
        "{%0,%1,%2,%3}, {%4,%5,%6,%7}, {%8,%9}, {%0,%1,%2,%3};"
        : "+f"(d[0]), "+f"(d[1]), "+f"(d[2]), "+f"(d[3])
        : "r"(a[0]), "r"(a[1]), "r"(a[2]), "r"(a[3]), "r"(b[0]), "r"(b[1]));
}

// ---------------- prep -----------------------------------------------------------
__global__ void split_x(const float* __restrict__ x) {
    int i = blockIdx.x * 256 + threadIdx.x;
    g_xh[i] = __float2half(x[i]);
}

// W [k][n] -> Wt [n][k]. z 0..2 -> Wq/Wk/Wv fp16; z==3 -> Wo bf16 hi/lo
__global__ void transpose_w(const float* __restrict__ Wq, const float* __restrict__ Wk,
                            const float* __restrict__ Wv, const float* __restrict__ Wo) {
    __shared__ float tile[32][33];
    int z = blockIdx.z;
    const float* W = (z == 0) ? Wq : (z == 1) ? Wk : (z == 2) ? Wv : Wo;
    int k0 = blockIdx.y * 32, n0 = blockIdx.x * 32;
    int tx = threadIdx.x, ty = threadIdx.y;
    tile[ty][tx] = W[(size_t)(k0 + ty) * DM + n0 + tx];
    __syncthreads();
    float v = tile[tx][ty];
    size_t o = (size_t)(n0 + ty) * DM + k0 + tx;
    if (z < 3) {
        g_wth[(size_t)z * DM * DM + o] = __float2half(v);
    } else {
        __nv_bfloat16 hi = __float2bfloat16(v);
        g_wothi[o] = hi;
        g_wotlo[o] = __float2bfloat16(v - __bfloat162float(hi));
    }
}

// ---------------- fp16 single-pass GEMM: C[M,N] = A[M,K] @ B[N,K]^T --------------
// 128x128x64 CTA tile, 8 warps (4m x 2n), 3-stage cp.async pipeline.
#define F_BK 64
#define F_STG 32768
#define F_OFF_B 16384
#define F_NSTAGE 3

// 128B rows (64 fp16), 8 x 16B segs; swizzle seg' = seg ^ (row & 7)
__device__ __forceinline__ uint32_t swz8(uint32_t row, uint32_t seg) {
    return row * 128 + ((seg ^ (row & 7)) << 4);
}

__device__ __forceinline__ void f16_load_chunk(
    uint32_t stage, int tid, int c, int m0, int n0, int K,
    const __half* A, const __half* B)
{
    #pragma unroll
    for (int mtx = 0; mtx < 2; mtx++) {
        const int r0 = (mtx == 0) ? m0 : n0;
        const __half* src = (mtx == 0) ? A : B;
        const uint32_t off = mtx ? F_OFF_B : 0;
        #pragma unroll
        for (int i = 0; i < 4; i++) {
            int lin = i * 256 + tid;              // 1024 x 16B per matrix
            int row = lin >> 3, seg = lin & 7;
            const void* g = src + (size_t)(r0 + row) * K + c * F_BK + seg * 8;
            cp16(stage + off + swz8(row, seg), g);
        }
    }
}

__global__ void __launch_bounds__(256) gemm_f16(
    const __half* __restrict__ A, const __half* __restrict__ B,
    float* __restrict__ C, int Nstride, int K)
{
    extern __shared__ __align__(1024) char dsm[];
    const uint32_t tiles = smem_u32(dsm);

    const int tid = threadIdx.x;
    const int m0 = blockIdx.y * 128, n0 = blockIdx.x * 128;
    const int nCh = K / F_BK;

    const int w = tid >> 5, lane = tid & 31;
    const int wm = (w & 3) * 32;
    const int wn = (w >> 2) * 64;

    float acc[2][8][4];
    #pragma unroll
    for (int i = 0; i < 2; i++)
        #pragma unroll
        for (int j = 0; j < 8; j++)
            #pragma unroll
            for (int e = 0; e < 4; e++) acc[i][j][e] = 0.f;

    f16_load_chunk(tiles, tid, 0, m0, n0, K, A, B); CP_COMMIT();
    f16_load_chunk(tiles + F_STG, tid, 1, m0, n0, K, A, B); CP_COMMIT();

    const int aRowL = lane & 15;
    const int aSegL = lane >> 4;
    const int bRowL = ((lane >> 4) & 1) * 8 + (lane & 7);
    const int bSegL = (lane >> 3) & 1;

    for (int c = 0; c < nCh; c++) {
        const uint32_t buf = tiles + (c % F_NSTAGE) * F_STG;
        CP_WAIT1();
        __syncthreads();
        if (c + 2 < nCh)
            f16_load_chunk(tiles + ((c + 2) % F_NSTAGE) * F_STG, tid, c + 2, m0, n0, K, A, B);
        CP_COMMIT();

        #pragma unroll
        for (int k16 = 0; k16 < 4; k16++) {
            uint32_t af[2][4], bf[4][4];
            #pragma unroll
            for (int mt = 0; mt < 2; mt++) {
                uint32_t row = wm + mt * 16 + aRowL;
                ldsm_x4(af[mt][0], af[mt][1], af[mt][2], af[mt][3],
                        buf + swz8(row, k16 * 2 + aSegL));
            }
            #pragma unroll
            for (int np = 0; np < 4; np++) {
                uint32_t row = wn + np * 16 + bRowL;
                ldsm_x4(bf[np][0], bf[np][1], bf[np][2], bf[np][3],
                        buf + F_OFF_B + swz8(row, k16 * 2 + bSegL));
            }
            #pragma unroll
            for (int mt = 0; mt < 2; mt++)
                #pragma unroll
                for (int np = 0; np < 4; np++)
                    #pragma unroll
                    for (int h = 0; h < 2; h++)
                        mma_f16(acc[mt][np * 2 + h], af[mt], &bf[np][h * 2]);
        }
        __syncthreads();
    }

    const int erow = lane >> 2, ecol = (lane & 3) * 2;
    #pragma unroll
    for (int mt = 0; mt < 2; mt++)
        #pragma unroll
        for (int nt = 0; nt < 8; nt++) {
            const float* d = acc[mt][nt];
            size_t r = (size_t)(m0 + wm + mt * 16 + erow);
            size_t col = n0 + wn + nt * 8 + ecol;
            *(float2*)&C[r * Nstride + col]       = make_float2(d[0], d[1]);
            *(float2*)&C[(r + 8) * Nstride + col] = make_float2(d[2], d[3]);
        }
}

// ---------------- bf16x3 GEMM (Wo): C[M,N] = A[M,K] @ B[N,K]^T -------------------
#define BK 32
#define NSTAGE 3
#define STG 32768
#define OFF_AHI 0
#define OFF_ALO 8192
#define OFF_BHI 16384
#define OFF_BLO 24576

__device__ __forceinline__ uint32_t swz(uint32_t row, uint32_t seg) {
    return row * 64 + ((seg ^ (row & 3)) << 4);
}

__device__ __forceinline__ void load_chunk(
    uint32_t stage, int tid, int c, int m0, int n0, int K,
    const __nv_bfloat16* Ahi, const __nv_bfloat16* Alo,
    const __nv_bfloat16* Bhi, const __nv_bfloat16* Blo)
{
    const __nv_bfloat16* srcs[4] = {Ahi, Alo, Bhi, Blo};
    const uint32_t offs[4] = {OFF_AHI, OFF_ALO, OFF_BHI, OFF_BLO};
    #pragma unroll
    for (int mtx = 0; mtx < 4; mtx++) {
        const int r0 = (mtx < 2) ? m0 : n0;
        const __nv_bfloat16* src = srcs[mtx];
        #pragma unroll
        for (int i = 0; i < 2; i++) {
            int lin = i * 256 + tid;
            int row = lin >> 2, seg = lin & 3;
            const void* g = src + (size_t)(r0 + row) * K + c * BK + seg * 8;
            cp16(stage + offs[mtx] + swz(row, seg), g);
        }
    }
}

__global__ void __launch_bounds__(256) gemm_mma(
    const __nv_bfloat16* __restrict__ Ahi, const __nv_bfloat16* __restrict__ Alo,
    const __nv_bfloat16* __restrict__ Bhi, const __nv_bfloat16* __restrict__ Blo,
    float* __restrict__ C, int Nstride, int K)
{
    extern __shared__ __align__(1024) char dsm[];
    const uint32_t tiles = smem_u32(dsm);

    const int tid = threadIdx.x;
    const int m0 = blockIdx.y * 128, n0 = blockIdx.x * 128;
    const int nCh = K / BK;

    const int w = tid >> 5, lane = tid & 31;
    const int wm = (w & 3) * 32;
    const int wn = (w >> 2) * 64;

    float acc[2][8][4];
    #pragma unroll
    for (int i = 0; i < 2; i++)
        #pragma unroll
        for (int j = 0; j < 8; j++)
            #pragma unroll
            for (int e = 0; e < 4; e++) acc[i][j][e] = 0.f;

    load_chunk(tiles, tid, 0, m0, n0, K, Ahi, Alo, Bhi, Blo); CP_COMMIT();
    load_chunk(tiles + STG, tid, 1, m0, n0, K, Ahi, Alo, Bhi, Blo); CP_COMMIT();

    const int aRowL = lane & 15;
    const int aSegL = lane >> 4;
    const int bRowL = ((lane >> 4) & 1) * 8 + (lane & 7);
    const int bSegL = (lane >> 3) & 1;

    for (int c = 0; c < nCh; c++) {
        const uint32_t buf = tiles + (c % NSTAGE) * STG;
        CP_WAIT1();
        __syncthreads();
        if (c + 2 < nCh)
            load_chunk(tiles + ((c + 2) % NSTAGE) * STG, tid, c + 2, m0, n0, K,
                       Ahi, Alo, Bhi, Blo);
        CP_COMMIT();

        #pragma unroll
        for (int k16 = 0; k16 < 2; k16++) {
            uint32_t aH[2][4], aL[2][4], bH[4][4], bL[4][4];
            #pragma unroll
            for (int mt = 0; mt < 2; mt++) {
                uint32_t row = wm + mt * 16 + aRowL;
                uint32_t off = swz(row, k16 * 2 + aSegL);
                ldsm_x4(aH[mt][0], aH[mt][1], aH[mt][2], aH[mt][3], buf + OFF_AHI + off);
                ldsm_x4(aL[mt][0], aL[mt][1], aL[mt][2], aL[mt][3], buf + OFF_ALO + off);
            }
            #pragma unroll
            for (int np = 0; np < 4; np++) {
                uint32_t row = wn + np * 16 + bRowL;
                uint32_t off = swz(row, k16 * 2 + bSegL);
                ldsm_x4(bH[np][0], bH[np][1], bH[np][2], bH[np][3], buf + OFF_BHI + off);
                ldsm_x4(bL[np][0], bL[np][1], bL[np][2], bL[np][3], buf + OFF_BLO + off);
            }
            #pragma unroll
            for (int mt = 0; mt < 2; mt++)
                #pragma unroll
                for (int np = 0; np < 4; np++)
                    #pragma unroll
                    for (int h = 0; h < 2; h++) {
                        float* d = acc[mt][np * 2 + h];
                        mma_bf16(d, aH[mt], &bH[np][h * 2]);
                        mma_bf16(d, aH[mt], &bL[np][h * 2]);
                        mma_bf16(d, aL[mt], &bH[np][h * 2]);
                    }
        }
        __syncthreads();
    }

    const int erow = lane >> 2, ecol = (lane & 3) * 2;
    #pragma unroll
    for (int mt = 0; mt < 2; mt++)
        #pragma unroll
        for (int nt = 0; nt < 8; nt++) {
            const float* d = acc[mt][nt];
            size_t r = (size_t)(m0 + wm + mt * 16 + erow);
            size_t col = n0 + wn + nt * 8 + ecol;
            *(float2*)&C[r * Nstride + col]       = make_float2(d[0], d[1]);
            *(float2*)&C[(r + 8) * Nstride + col] = make_float2(d[2], d[3]);
        }
}

// ---------------- RoPE for K only: [S,3072] -> [H,S,D] -------------------------
__global__ void rope_k(const float* __restrict__ cosT, const float* __restrict__ sinT) {
    const int idx = blockIdx.x * 256 + threadIdx.x;
    const int d = idx & 31;
    const int h = (idx >> 5) & 15;
    const int s = idx >> 9;
    const int base = s * 3072 + 1024 + h * HD;
    const float k0 = g_lin[base + d];
    const float k1 = g_lin[base + d + 32];
    const float c = cosT[s * 32 + d], sn = sinT[s * 32 + d];
    const int dst = (h * SEQ + s) * HD + d;
    g_kh[dst]      = k0 * c - k1 * sn;
    g_kh[dst + 32] = k1 * c + k0 * sn;
}

// ---------------- sparse attention: 4 queries / 256-thread block ----------------
__global__ void __launch_bounds__(256) attn(const int* __restrict__ anchors,
                                            const float* __restrict__ cosT,
                                            const float* __restrict__ sinT) {
    const int h = blockIdx.y;
    const int tid = threadIdx.x;
    const int ql = tid >> 6;
    const int j = tid & 63;
    const int s = blockIdx.x * QPB + ql;

    __shared__ float sqraw[QPB][64];
    __shared__ float4 sq4[QPB][16];
    __shared__ float swt[QPB][64];
    __shared__ int sidx[QPB][64];
    __shared__ float wred[QPB][2][2];

    sqraw[ql][j] = g_lin[s * 3072 + h * HD + j];

    const int slot = j >> 4, t = j & 15;
    const int tile = (slot < NANCH) ? anchors[(h * SEQ + s) * NANCH + slot] : (s >> 4);
    int kidx = min(max(tile * 16 + t, 0), SEQ - 1);
    const bool masked = kidx > s;
    sidx[ql][j] = kidx;
    __syncthreads();

    {
        const float c = cosT[s * 32 + (j & 31)], sn = sinT[s * 32 + (j & 31)];
        const float v = sqraw[ql][j];
        const float p = sqraw[ql][j ^ 32];
        ((float*)sq4[ql])[j] = (j < 32) ? (v * c - p * sn) : (v * c + p * sn);
    }
    __syncthreads();

    float logit = -1e30f;
    if (!masked) {
        const float4* kr = (const float4*)&g_kh[((size_t)h * SEQ + kidx) * HD];
        float acc = 0.f;
        #pragma unroll
        for (int dd = 0; dd < 16; dd++) {
            const float4 kv = kr[dd];
            const float4 qv = sq4[ql][dd];
            acc = fmaf(kv.x, qv.x, acc);
            acc = fmaf(kv.y, qv.y, acc);
            acc = fmaf(kv.z, qv.z, acc);
            acc = fmaf(kv.w, qv.w, acc);
        }
        logit = acc * 0.125f;
    }

    const int wq = (tid >> 5) & 1, lane = tid & 31;
    float m = logit;
    #pragma unroll
    for (int off = 16; off; off >>= 1) m = fmaxf(m, __shfl_xor_sync(~0u, m, off));
    if (lane == 0) wred[ql][0][wq] = m;
    __syncthreads();
    m = fmaxf(wred[ql][0][0], wred[ql][0][1]);

    const float e = masked ? 0.f : __expf(logit - m);
    float ssum = e;
    #pragma unroll
    for (int off = 16; off; off >>= 1) ssum += __shfl_xor_sync(~0u, ssum, off);
    if (lane == 0) wred[ql][1][wq] = ssum;
    __syncthreads();
    ssum = wred[ql][1][0] + wred[ql][1][1];

    swt[ql][j] = e / ssum;
    __syncthreads();

    const float* vbase = g_lin + 2048 + h * HD + j;
    float acc = 0.f;
    #pragma unroll 16
    for (int jj = 0; jj < 64; jj++)
        acc = fmaf(swt[ql][jj], vbase[(size_t)sidx[ql][jj] * 3072], acc);

    __nv_bfloat16 hi = __float2bfloat16(acc);
    const int o = s * DM + h * HD + j;
    g_athi[o] = hi;
    g_atlo[o] = __float2bfloat16(acc - __bfloat162float(hi));
}

// ---------------- launch ---------------------------------------------------------
extern "C" void kernel_launch(void* const* d_in, const int* in_sizes, int n_in,
                              void* d_out, int out_size)
{
    const float* x    = (const float*)d_in[0];
    const float* Wq   = (const float*)d_in[1];
    const float* Wk   = (const float*)d_in[2];
    const float* Wv   = (const float*)d_in[3];
    const float* Wo   = (const float*)d_in[4];
    const float* cosT = (const float*)d_in[5];
    const float* sinT = (const float*)d_in[6];
    const int* anchors = (const int*)d_in[7];
    float* out = (float*)d_out;

    const int SMEM_F = F_NSTAGE * F_STG;   // 96 KB
    const int SMEM_B = NSTAGE * STG;       // 96 KB
    cudaFuncSetAttribute(gemm_f16, cudaFuncAttributeMaxDynamicSharedMemorySize, SMEM_F);
    cudaFuncSetAttribute(gemm_mma, cudaFuncAttributeMaxDynamicSharedMemorySize, SMEM_B);

    float* lin = nullptr;
    __half *xh = nullptr, *wth = nullptr;
    __nv_bfloat16 *wothi = nullptr, *wotlo = nullptr, *athi = nullptr, *atlo = nullptr;
    cudaGetSymbolAddress((void**)&lin, g_lin);
    cudaGetSymbolAddress((void**)&xh, g_xh);
    cudaGetSymbolAddress((void**)&wth, g_wth);
    cudaGetSymbolAddress((void**)&wothi, g_wothi);
    cudaGetSymbolAddress((void**)&wotlo, g_wotlo);
    cudaGetSymbolAddress((void**)&athi, g_athi);
    cudaGetSymbolAddress((void**)&atlo, g_atlo);

    split_x<<<(SEQ * DM) / 256, 256>>>(x);
    transpose_w<<<dim3(32, 32, 4), dim3(32, 32)>>>(Wq, Wk, Wv, Wo);

    // qkv = x @ [Wq|Wk|Wv] -> g_lin [2048, 3072]  (fp16 single-pass)
    gemm_f16<<<dim3(24, 16), 256, SMEM_F>>>(xh, wth, lin, 3072, DM);

    rope_k<<<(SEQ * NH * 32) / 256, 256>>>(cosT, sinT);
    attn<<<dim3(SEQ / QPB, NH), 256>>>(anchors, cosT, sinT);

    // out = att @ Wo  (bf16x3 for accuracy headroom)
    gemm_mma<<<dim3(8, 16), 256, SMEM_B>>>(athi, atlo, wothi, wotlo, out, DM, DM);
}

// round 6
// speedup vs baseline: 4.8388x; 1.3069x over previous
#include <cuda_runtime.h>
#include <cuda_bf16.h>
#include <cuda_fp16.h>
#include <cstdint>

#define SEQ 2048
#define DM 1024
#define NH 16
#define HD 64
#define NANCH 3
#define QPB 4

// ---------------- scratch ------------------------------------------------------
__device__ float g_lin[SEQ * 3072];          // fused q|k|v rows [S, 3072] fp32
__device__ __half g_khh[NH * SEQ * HD];      // K after RoPE, fp16 [H,S,D] (128B rows)
__device__ __half g_vhh[SEQ * DM];           // V fp16 [S, H*D]
__device__ __half g_xh[SEQ * DM];            // x fp16
__device__ __half g_wth[3072 * DM];          // [n,k] Wq|Wk|Wv^T fp16
__device__ __half g_woth[DM * DM];           // [n,k] Wo^T fp16
__device__ __half g_ath[SEQ * DM];           // attn out fp16 [S, H*D]

// ---------------- PTX helpers --------------------------------------------------
__device__ __forceinline__ uint32_t smem_u32(const void* p) {
    uint32_t a;
    asm("{ .reg .u64 t; cvta.to.shared.u64 t, %1; cvt.u32.u64 %0, t; }" : "=r"(a) : "l"(p));
    return a;
}
__device__ __forceinline__ void cp16(uint32_t s, const void* g) {
    asm volatile("cp.async.cg.shared.global [%0], [%1], 16;" :: "r"(s), "l"(g));
}
#define CP_COMMIT() asm volatile("cp.async.commit_group;" ::: "memory")
#define CP_WAIT1()  asm volatile("cp.async.wait_group 1;" ::: "memory")

__device__ __forceinline__ void ldsm_x4(uint32_t& r0, uint32_t& r1, uint32_t& r2,
                                        uint32_t& r3, uint32_t a) {
    asm volatile("ldmatrix.sync.aligned.m8n8.x4.shared.b16 {%0,%1,%2,%3}, [%4];"
                 : "=r"(r0), "=r"(r1), "=r"(r2), "=r"(r3) : "r"(a));
}
__device__ __forceinline__ void mma_f16(float* d, const uint32_t* a, const uint32_t* b) {
    asm volatile(
        "mma.sync.aligned.m16n8k16.row.col.f32.f16.f16.f32 "
        "{%0,%1,%2,%3}, {%4,%5,%6,%7}, {%8,%9}, {%0,%1,%2,%3};"
        : "+f"(d[0]), "+f"(d[1]), "+f"(d[2]), "+f"(d[3])
        : "r"(a[0]), "r"(a[1]), "r"(a[2]), "r"(a[3]), "r"(b[0]), "r"(b[1]));
}

// ---------------- prep -----------------------------------------------------------
__global__ void split_x(const float* __restrict__ x) {
    int i = blockIdx.x * 256 + threadIdx.x;
    g_xh[i] = __float2half(x[i]);
}

// W [k][n] -> Wt [n][k] fp16. z 0..2 -> Wq/Wk/Wv; z==3 -> Wo
__global__ void transpose_w(const float* __restrict__ Wq, const float* __restrict__ Wk,
                            const float* __restrict__ Wv, const float* __restrict__ Wo) {
    __shared__ float tile[32][33];
    int z = blockIdx.z;
    const float* W = (z == 0) ? Wq : (z == 1) ? Wk : (z == 2) ? Wv : Wo;
    __half* dst = (z < 3) ? (g_wth + (size_t)z * DM * DM) : g_woth;
    int k0 = blockIdx.y * 32, n0 = blockIdx.x * 32;
    int tx = threadIdx.x, ty = threadIdx.y;
    tile[ty][tx] = W[(size_t)(k0 + ty) * DM + n0 + tx];
    __syncthreads();
    dst[(size_t)(n0 + ty) * DM + k0 + tx] = __float2half(tile[tx][ty]);
}

// ---------------- fp16 GEMM: C[M,N] = A[M,K] @ B[N,K]^T --------------------------
// 128x128x64 CTA tile, 8 warps (4m x 2n), 3-stage cp.async pipeline.
#define F_BK 64
#define F_STG 32768
#define F_OFF_B 16384
#define F_NSTAGE 3

__device__ __forceinline__ uint32_t swz8(uint32_t row, uint32_t seg) {
    return row * 128 + ((seg ^ (row & 7)) << 4);
}

__device__ __forceinline__ void f16_load_chunk(
    uint32_t stage, int tid, int c, int m0, int n0, int K,
    const __half* A, const __half* B)
{
    #pragma unroll
    for (int mtx = 0; mtx < 2; mtx++) {
        const int r0 = (mtx == 0) ? m0 : n0;
        const __half* src = (mtx == 0) ? A : B;
        const uint32_t off = mtx ? F_OFF_B : 0;
        #pragma unroll
        for (int i = 0; i < 4; i++) {
            int lin = i * 256 + tid;
            int row = lin >> 3, seg = lin & 7;
            const void* g = src + (size_t)(r0 + row) * K + c * F_BK + seg * 8;
            cp16(stage + off + swz8(row, seg), g);
        }
    }
}

__global__ void __launch_bounds__(256) gemm_f16(
    const __half* __restrict__ A, const __half* __restrict__ B,
    float* __restrict__ C, int Nstride, int K)
{
    extern __shared__ __align__(1024) char dsm[];
    const uint32_t tiles = smem_u32(dsm);

    const int tid = threadIdx.x;
    const int m0 = blockIdx.y * 128, n0 = blockIdx.x * 128;
    const int nCh = K / F_BK;

    const int w = tid >> 5, lane = tid & 31;
    const int wm = (w & 3) * 32;
    const int wn = (w >> 2) * 64;

    float acc[2][8][4];
    #pragma unroll
    for (int i = 0; i < 2; i++)
        #pragma unroll
        for (int j = 0; j < 8; j++)
            #pragma unroll
            for (int e = 0; e < 4; e++) acc[i][j][e] = 0.f;

    f16_load_chunk(tiles, tid, 0, m0, n0, K, A, B); CP_COMMIT();
    f16_load_chunk(tiles + F_STG, tid, 1, m0, n0, K, A, B); CP_COMMIT();

    const int aRowL = lane & 15;
    const int aSegL = lane >> 4;
    const int bRowL = ((lane >> 4) & 1) * 8 + (lane & 7);
    const int bSegL = (lane >> 3) & 1;

    for (int c = 0; c < nCh; c++) {
        const uint32_t buf = tiles + (c % F_NSTAGE) * F_STG;
        CP_WAIT1();
        __syncthreads();
        if (c + 2 < nCh)
            f16_load_chunk(tiles + ((c + 2) % F_NSTAGE) * F_STG, tid, c + 2, m0, n0, K, A, B);
        CP_COMMIT();

        #pragma unroll
        for (int k16 = 0; k16 < 4; k16++) {
            uint32_t af[2][4], bf[4][4];
            #pragma unroll
            for (int mt = 0; mt < 2; mt++) {
                uint32_t row = wm + mt * 16 + aRowL;
                ldsm_x4(af[mt][0], af[mt][1], af[mt][2], af[mt][3],
                        buf + swz8(row, k16 * 2 + aSegL));
            }
            #pragma unroll
            for (int np = 0; np < 4; np++) {
                uint32_t row = wn + np * 16 + bRowL;
                ldsm_x4(bf[np][0], bf[np][1], bf[np][2], bf[np][3],
                        buf + F_OFF_B + swz8(row, k16 * 2 + bSegL));
            }
            #pragma unroll
            for (int mt = 0; mt < 2; mt++)
                #pragma unroll
                for (int np = 0; np < 4; np++)
                    #pragma unroll
                    for (int h = 0; h < 2; h++)
                        mma_f16(acc[mt][np * 2 + h], af[mt], &bf[np][h * 2]);
        }
        __syncthreads();
    }

    const int erow = lane >> 2, ecol = (lane & 3) * 2;
    #pragma unroll
    for (int mt = 0; mt < 2; mt++)
        #pragma unroll
        for (int nt = 0; nt < 8; nt++) {
            const float* d = acc[mt][nt];
            size_t r = (size_t)(m0 + wm + mt * 16 + erow);
            size_t col = n0 + wn + nt * 8 + ecol;
            *(float2*)&C[r * Nstride + col]       = make_float2(d[0], d[1]);
            *(float2*)&C[(r + 8) * Nstride + col] = make_float2(d[2], d[3]);
        }
}

// ---------------- K RoPE + K/V fp16 downconvert ---------------------------------
__global__ void convert_kv(const float* __restrict__ cosT, const float* __restrict__ sinT) {
    const int idx = blockIdx.x * 256 + threadIdx.x;   // (s, h, d<32)
    const int d = idx & 31;
    const int h = (idx >> 5) & 15;
    const int s = idx >> 9;
    const int base = s * 3072 + 1024 + h * HD;
    const float k0 = g_lin[base + d];
    const float k1 = g_lin[base + d + 32];
    const float c = cosT[s * 32 + d], sn = sinT[s * 32 + d];
    const int kdst = (h * SEQ + s) * HD + d;
    g_khh[kdst]      = __float2half(k0 * c - k1 * sn);
    g_khh[kdst + 32] = __float2half(k1 * c + k0 * sn);
    const int vdst = s * DM + h * HD + d;
    g_vhh[vdst]      = __float2half(g_lin[base + 1024 + d]);
    g_vhh[vdst + 32] = __float2half(g_lin[base + 1024 + d + 32]);
}

// ---------------- sparse attention: 4 queries / 256-thread block ----------------
__global__ void __launch_bounds__(256) attn(const int* __restrict__ anchors,
                                            const float* __restrict__ cosT,
                                            const float* __restrict__ sinT) {
    const int h = blockIdx.y;
    const int tid = threadIdx.x;
    const int ql = tid >> 6;
    const int j = tid & 63;
    const int s = blockIdx.x * QPB + ql;

    __shared__ float sqraw[QPB][64];
    __shared__ float sqf[QPB][64];
    __shared__ float swt[QPB][64];
    __shared__ int sidx[QPB][64];
    __shared__ float wred[QPB][2][2];

    sqraw[ql][j] = g_lin[s * 3072 + h * HD + j];

    const int slot = j >> 4, t = j & 15;
    const int tile = (slot < NANCH) ? anchors[(h * SEQ + s) * NANCH + slot] : (s >> 4);
    int kidx = min(max(tile * 16 + t, 0), SEQ - 1);
    const bool masked = kidx > s;
    sidx[ql][j] = kidx;
    __syncthreads();

    // RoPE on q
    {
        const float c = cosT[s * 32 + (j & 31)], sn = sinT[s * 32 + (j & 31)];
        const float v = sqraw[ql][j];
        const float p = sqraw[ql][j ^ 32];
        sqf[ql][j] = (j < 32) ? (v * c - p * sn) : (v * c + p * sn);
    }
    __syncthreads();

    // logit: thread j vs gathered fp16 key row (128B = one L2 line)
    float logit = -1e30f;
    if (!masked) {
        const float4* kr = (const float4*)&g_khh[((size_t)h * SEQ + kidx) * HD];
        float acc = 0.f;
        #pragma unroll
        for (int dd = 0; dd < 8; dd++) {
            const float4 raw = kr[dd];
            const uint32_t* u = (const uint32_t*)&raw;
            #pragma unroll
            for (int e = 0; e < 4; e++) {
                const float2 kv = __half22float2(*(const __half2*)&u[e]);
                acc = fmaf(kv.x, sqf[ql][dd * 8 + e * 2], acc);
                acc = fmaf(kv.y, sqf[ql][dd * 8 + e * 2 + 1], acc);
            }
        }
        logit = acc * 0.125f;
    }

    const int wq = (tid >> 5) & 1, lane = tid & 31;
    float m = logit;
    #pragma unroll
    for (int off = 16; off; off >>= 1) m = fmaxf(m, __shfl_xor_sync(~0u, m, off));
    if (lane == 0) wred[ql][0][wq] = m;
    __syncthreads();
    m = fmaxf(wred[ql][0][0], wred[ql][0][1]);

    const float e = masked ? 0.f : __expf(logit - m);
    float ssum = e;
    #pragma unroll
    for (int off = 16; off; off >>= 1) ssum += __shfl_xor_sync(~0u, ssum, off);
    if (lane == 0) wred[ql][1][wq] = ssum;
    __syncthreads();
    ssum = wred[ql][1][0] + wred[ql][1][1];

    swt[ql][j] = e / ssum;
    __syncthreads();

    // output: thread j owns dim j; fp16 V gather (coalesced in j)
    const __half* vbase = g_vhh + h * HD + j;
    float acc = 0.f;
    #pragma unroll 16
    for (int jj = 0; jj < 64; jj++)
        acc = fmaf(swt[ql][jj], __half2float(vbase[(size_t)sidx[ql][jj] * DM]), acc);

    g_ath[s * DM + h * HD + j] = __float2half(acc);
}

// ---------------- launch ---------------------------------------------------------
extern "C" void kernel_launch(void* const* d_in, const int* in_sizes, int n_in,
                              void* d_out, int out_size)
{
    const float* x    = (const float*)d_in[0];
    const float* Wq   = (const float*)d_in[1];
    const float* Wk   = (const float*)d_in[2];
    const float* Wv   = (const float*)d_in[3];
    const float* Wo   = (const float*)d_in[4];
    const float* cosT = (const float*)d_in[5];
    const float* sinT = (const float*)d_in[6];
    const int* anchors = (const int*)d_in[7];
    float* out = (float*)d_out;

    const int SMEM_F = F_NSTAGE * F_STG;   // 96 KB
    cudaFuncSetAttribute(gemm_f16, cudaFuncAttributeMaxDynamicSharedMemorySize, SMEM_F);

    float* lin = nullptr;
    __half *xh = nullptr, *wth = nullptr, *woth = nullptr, *ath = nullptr;
    cudaGetSymbolAddress((void**)&lin, g_lin);
    cudaGetSymbolAddress((void**)&xh, g_xh);
    cudaGetSymbolAddress((void**)&wth, g_wth);
    cudaGetSymbolAddress((void**)&woth, g_woth);
    cudaGetSymbolAddress((void**)&ath, g_ath);

    split_x<<<(SEQ * DM) / 256, 256>>>(x);
    transpose_w<<<dim3(32, 32, 4), dim3(32, 32)>>>(Wq, Wk, Wv, Wo);

    // qkv = x @ [Wq|Wk|Wv] -> g_lin [2048, 3072]
    gemm_f16<<<dim3(24, 16), 256, SMEM_F>>>(xh, wth, lin, 3072, DM);

    convert_kv<<<(SEQ * NH * 32) / 256, 256>>>(cosT, sinT);
    attn<<<dim3(SEQ / QPB, NH), 256>>>(anchors, cosT, sinT);

    // out = att @ Wo (fp16)
    gemm_f16<<<dim3(8, 16), 256, SMEM_F>>>(ath, woth, out, DM, DM);
}

// round 7
// speedup vs baseline: 5.3826x; 1.1124x over previous
#include <cuda_runtime.h>
#include <cuda_fp16.h>
#include <cstdint>

#define SEQ 2048
#define DM 1024
#define NH 16
#define HD 64
#define NANCH 3
#define QPB 4

// ---------------- scratch ------------------------------------------------------
__device__ __half g_qh16[SEQ * DM];          // Q after RoPE, fp16 [S, H*D]
__device__ __half g_khh[NH * SEQ * HD];      // K after RoPE, fp16 [H,S,D] (128B rows)
__device__ __half g_vhh[SEQ * DM];           // V fp16 [S, H*D]
__device__ __half g_xh[SEQ * DM];            // x fp16
__device__ __half g_wth[3072 * DM];          // [n,k] Wq|Wk|Wv^T fp16
__device__ __half g_woth[DM * DM];           // [n,k] Wo^T fp16
__device__ __half g_ath[SEQ * DM];           // attn out fp16 [S, H*D]

// ---------------- PTX helpers --------------------------------------------------
__device__ __forceinline__ uint32_t smem_u32(const void* p) {
    uint32_t a;
    asm("{ .reg .u64 t; cvta.to.shared.u64 t, %1; cvt.u32.u64 %0, t; }" : "=r"(a) : "l"(p));
    return a;
}
__device__ __forceinline__ void cp16(uint32_t s, const void* g) {
    asm volatile("cp.async.cg.shared.global [%0], [%1], 16;" :: "r"(s), "l"(g));
}
#define CP_COMMIT() asm volatile("cp.async.commit_group;" ::: "memory")
#define CP_WAIT1()  asm volatile("cp.async.wait_group 1;" ::: "memory")

__device__ __forceinline__ void ldsm_x4(uint32_t& r0, uint32_t& r1, uint32_t& r2,
                                        uint32_t& r3, uint32_t a) {
    asm volatile("ldmatrix.sync.aligned.m8n8.x4.shared.b16 {%0,%1,%2,%3}, [%4];"
                 : "=r"(r0), "=r"(r1), "=r"(r2), "=r"(r3) : "r"(a));
}
__device__ __forceinline__ void mma_f16(float* d, const uint32_t* a, const uint32_t* b) {
    asm volatile(
        "mma.sync.aligned.m16n8k16.row.col.f32.f16.f16.f32 "
        "{%0,%1,%2,%3}, {%4,%5,%6,%7}, {%8,%9}, {%0,%1,%2,%3};"
        : "+f"(d[0]), "+f"(d[1]), "+f"(d[2]), "+f"(d[3])
        : "r"(a[0]), "r"(a[1]), "r"(a[2]), "r"(a[3]), "r"(b[0]), "r"(b[1]));
}

// ---------------- prep -----------------------------------------------------------
__global__ void split_x(const float* __restrict__ x) {
    int i = blockIdx.x * 256 + threadIdx.x;
    g_xh[i] = __float2half(x[i]);
}

// W [k][n] -> Wt [n][k] fp16. z 0..2 -> Wq/Wk/Wv; z==3 -> Wo
__global__ void transpose_w(const float* __restrict__ Wq, const float* __restrict__ Wk,
                            const float* __restrict__ Wv, const float* __restrict__ Wo) {
    __shared__ float tile[32][33];
    int z = blockIdx.z;
    const float* W = (z == 0) ? Wq : (z == 1) ? Wk : (z == 2) ? Wv : Wo;
    __half* dst = (z < 3) ? (g_wth + (size_t)z * DM * DM) : g_woth;
    int k0 = blockIdx.y * 32, n0 = blockIdx.x * 32;
    int tx = threadIdx.x, ty = threadIdx.y;
    tile[ty][tx] = W[(size_t)(k0 + ty) * DM + n0 + tx];
    __syncthreads();
    dst[(size_t)(n0 + ty) * DM + k0 + tx] = __float2half(tile[tx][ty]);
}

// ---------------- fp16 GEMM: C[M,N] = A[M,K] @ B[N,K]^T --------------------------
// 128x128x64 CTA tile, 8 warps (4m x 2n), 3-stage cp.async pipeline.
// mode 0: QKV fused epilogue (RoPE on q/k, fp16 split outputs)
// mode 1: plain fp32 C write
#define F_BK 64
#define F_STG 32768
#define F_OFF_B 16384
#define F_NSTAGE 3

__device__ __forceinline__ uint32_t swz8(uint32_t row, uint32_t seg) {
    return row * 128 + ((seg ^ (row & 7)) << 4);
}

__device__ __forceinline__ void f16_load_chunk(
    uint32_t stage, int tid, int c, int m0, int n0, int K,
    const __half* A, const __half* B)
{
    #pragma unroll
    for (int mtx = 0; mtx < 2; mtx++) {
        const int r0 = (mtx == 0) ? m0 : n0;
        const __half* src = (mtx == 0) ? A : B;
        const uint32_t off = mtx ? F_OFF_B : 0;
        #pragma unroll
        for (int i = 0; i < 4; i++) {
            int lin = i * 256 + tid;
            int row = lin >> 3, seg = lin & 7;
            const void* g = src + (size_t)(r0 + row) * K + c * F_BK + seg * 8;
            cp16(stage + off + swz8(row, seg), g);
        }
    }
}

__global__ void __launch_bounds__(256) gemm_f16(
    const __half* __restrict__ A, const __half* __restrict__ B,
    float* __restrict__ C, int Nstride, int K, int mode,
    __half* __restrict__ Qout, __half* __restrict__ Kout, __half* __restrict__ Vout,
    const float* __restrict__ cosT, const float* __restrict__ sinT)
{
    extern __shared__ __align__(1024) char dsm[];
    const uint32_t tiles = smem_u32(dsm);

    const int tid = threadIdx.x;
    const int m0 = blockIdx.y * 128, n0 = blockIdx.x * 128;
    const int nCh = K / F_BK;

    const int w = tid >> 5, lane = tid & 31;
    const int wm = (w & 3) * 32;
    const int wn = (w >> 2) * 64;

    float acc[2][8][4];
    #pragma unroll
    for (int i = 0; i < 2; i++)
        #pragma unroll
        for (int j = 0; j < 8; j++)
            #pragma unroll
            for (int e = 0; e < 4; e++) acc[i][j][e] = 0.f;

    f16_load_chunk(tiles, tid, 0, m0, n0, K, A, B); CP_COMMIT();
    f16_load_chunk(tiles + F_STG, tid, 1, m0, n0, K, A, B); CP_COMMIT();

    const int aRowL = lane & 15;
    const int aSegL = lane >> 4;
    const int bRowL = ((lane >> 4) & 1) * 8 + (lane & 7);
    const int bSegL = (lane >> 3) & 1;

    for (int c = 0; c < nCh; c++) {
        const uint32_t buf = tiles + (c % F_NSTAGE) * F_STG;
        CP_WAIT1();
        __syncthreads();
        if (c + 2 < nCh)
            f16_load_chunk(tiles + ((c + 2) % F_NSTAGE) * F_STG, tid, c + 2, m0, n0, K, A, B);
        CP_COMMIT();

        #pragma unroll
        for (int k16 = 0; k16 < 4; k16++) {
            uint32_t af[2][4], bf[4][4];
            #pragma unroll
            for (int mt = 0; mt < 2; mt++) {
                uint32_t row = wm + mt * 16 + aRowL;
                ldsm_x4(af[mt][0], af[mt][1], af[mt][2], af[mt][3],
                        buf + swz8(row, k16 * 2 + aSegL));
            }
            #pragma unroll
            for (int np = 0; np < 4; np++) {
                uint32_t row = wn + np * 16 + bRowL;
                ldsm_x4(bf[np][0], bf[np][1], bf[np][2], bf[np][3],
                        buf + F_OFF_B + swz8(row, k16 * 2 + bSegL));
            }
            #pragma unroll
            for (int mt = 0; mt < 2; mt++)
                #pragma unroll
                for (int np = 0; np < 4; np++)
                    #pragma unroll
                    for (int h = 0; h < 2; h++)
                        mma_f16(acc[mt][np * 2 + h], af[mt], &bf[np][h * 2]);
        }
        __syncthreads();
    }

    const int erow = lane >> 2, ecol = (lane & 3) * 2;

    if (mode == 0) {
        // QKV fused epilogue. Warp col span = 1 head. z = proj selector.
        const int ncol = n0 + wn;
        const int zsel = ncol >> 10;
        const int hh = (ncol >> 6) & 15;
        #pragma unroll
        for (int mt = 0; mt < 2; mt++) {
            #pragma unroll
            for (int rsel = 0; rsel < 2; rsel++) {
                const int s = m0 + wm + mt * 16 + erow + rsel * 8;
                if (zsel == 2) {
                    __half* vb = Vout + (size_t)s * DM + hh * HD;
                    #pragma unroll
                    for (int nt = 0; nt < 8; nt++)
                        *(__half2*)(vb + nt * 8 + ecol) =
                            __floats2half2_rn(acc[mt][nt][rsel * 2], acc[mt][nt][rsel * 2 + 1]);
                } else {
                    __half* ob = (zsel == 0) ? (Qout + (size_t)s * DM + hh * HD)
                                             : (Kout + ((size_t)hh * SEQ + s) * HD);
                    #pragma unroll
                    for (int nt = 0; nt < 4; nt++) {
                        const int d0 = nt * 8 + ecol;
                        const float c0 = cosT[s * 32 + d0],     sn0 = sinT[s * 32 + d0];
                        const float c1 = cosT[s * 32 + d0 + 1], sn1 = sinT[s * 32 + d0 + 1];
                        const float a0 = acc[mt][nt][rsel * 2],     a1 = acc[mt][nt][rsel * 2 + 1];
                        const float b0 = acc[mt][nt + 4][rsel * 2], b1 = acc[mt][nt + 4][rsel * 2 + 1];
                        *(__half2*)(ob + d0) =
                            __floats2half2_rn(a0 * c0 - b0 * sn0, a1 * c1 - b1 * sn1);
                        *(__half2*)(ob + d0 + 32) =
                            __floats2half2_rn(b0 * c0 + a0 * sn0, b1 * c1 + a1 * sn1);
                    }
                }
            }
        }
    } else {
        #pragma unroll
        for (int mt = 0; mt < 2; mt++)
            #pragma unroll
            for (int nt = 0; nt < 8; nt++) {
                const float* d = acc[mt][nt];
                size_t r = (size_t)(m0 + wm + mt * 16 + erow);
                size_t col = n0 + wn + nt * 8 + ecol;
                *(float2*)&C[r * Nstride + col]       = make_float2(d[0], d[1]);
                *(float2*)&C[(r + 8) * Nstride + col] = make_float2(d[2], d[3]);
            }
    }
}

// ---------------- sparse attention: 4 queries / 256-thread block ----------------
__global__ void __launch_bounds__(256) attn(const int* __restrict__ anchors) {
    const int h = blockIdx.y;
    const int tid = threadIdx.x;
    const int ql = tid >> 6;
    const int j = tid & 63;
    const int s = blockIdx.x * QPB + ql;

    __shared__ float sqf[QPB][64];
    __shared__ float swt[QPB][64];
    __shared__ int sidx[QPB][64];
    __shared__ float wred[QPB][2][2];

    sqf[ql][j] = __half2float(g_qh16[(size_t)s * DM + h * HD + j]);

    const int slot = j >> 4, t = j & 15;
    const int tile = (slot < NANCH) ? anchors[(h * SEQ + s) * NANCH + slot] : (s >> 4);
    int kidx = min(max(tile * 16 + t, 0), SEQ - 1);
    const bool masked = kidx > s;
    sidx[ql][j] = kidx;
    __syncthreads();

    // logit: thread j vs gathered fp16 key row (128B = one L2 line)
    float logit = -1e30f;
    if (!masked) {
        const float4* kr = (const float4*)&g_khh[((size_t)h * SEQ + kidx) * HD];
        float acc = 0.f;
        #pragma unroll
        for (int dd = 0; dd < 8; dd++) {
            const float4 raw = kr[dd];
            const uint32_t* u = (const uint32_t*)&raw;
            #pragma unroll
            for (int e = 0; e < 4; e++) {
                const float2 kv = __half22float2(*(const __half2*)&u[e]);
                acc = fmaf(kv.x, sqf[ql][dd * 8 + e * 2], acc);
                acc = fmaf(kv.y, sqf[ql][dd * 8 + e * 2 + 1], acc);
            }
        }
        logit = acc * 0.125f;
    }

    const int wq = (tid >> 5) & 1, lane = tid & 31;
    float m = logit;
    #pragma unroll
    for (int off = 16; off; off >>= 1) m = fmaxf(m, __shfl_xor_sync(~0u, m, off));
    if (lane == 0) wred[ql][0][wq] = m;
    __syncthreads();
    m = fmaxf(wred[ql][0][0], wred[ql][0][1]);

    const float e = masked ? 0.f : __expf(logit - m);
    float ssum = e;
    #pragma unroll
    for (int off = 16; off; off >>= 1) ssum += __shfl_xor_sync(~0u, ssum, off);
    if (lane == 0) wred[ql][1][wq] = ssum;
    __syncthreads();
    ssum = wred[ql][1][0] + wred[ql][1][1];

    swt[ql][j] = e / ssum;
    __syncthreads();

    // output: thread j owns dim j; fp16 V gather (coalesced in j)
    const __half* vbase = g_vhh + h * HD + j;
    float acc = 0.f;
    #pragma unroll 16
    for (int jj = 0; jj < 64; jj++)
        acc = fmaf(swt[ql][jj], __half2float(vbase[(size_t)sidx[ql][jj] * DM]), acc);

    g_ath[(size_t)s * DM + h * HD + j] = __float2half(acc);
}

// ---------------- launch ---------------------------------------------------------
extern "C" void kernel_launch(void* const* d_in, const int* in_sizes, int n_in,
                              void* d_out, int out_size)
{
    const float* x    = (const float*)d_in[0];
    const float* Wq   = (const float*)d_in[1];
    const float* Wk   = (const float*)d_in[2];
    const float* Wv   = (const float*)d_in[3];
    const float* Wo   = (const float*)d_in[4];
    const float* cosT = (const float*)d_in[5];
    const float* sinT = (const float*)d_in[6];
    const int* anchors = (const int*)d_in[7];
    float* out = (float*)d_out;

    const int SMEM_F = F_NSTAGE * F_STG;   // 96 KB
    cudaFuncSetAttribute(gemm_f16, cudaFuncAttributeMaxDynamicSharedMemorySize, SMEM_F);

    __half *xh = nullptr, *wth = nullptr, *woth = nullptr, *ath = nullptr;
    __half *qh = nullptr, *kh = nullptr, *vh = nullptr;
    cudaGetSymbolAddress((void**)&xh, g_xh);
    cudaGetSymbolAddress((void**)&wth, g_wth);
    cudaGetSymbolAddress((void**)&woth, g_woth);
    cudaGetSymbolAddress((void**)&ath, g_ath);
    cudaGetSymbolAddress((void**)&qh, g_qh16);
    cudaGetSymbolAddress((void**)&kh, g_khh);
    cudaGetSymbolAddress((void**)&vh, g_vhh);

    split_x<<<(SEQ * DM) / 256, 256>>>(x);
    transpose_w<<<dim3(32, 32, 4), dim3(32, 32)>>>(Wq, Wk, Wv, Wo);

    // QKV GEMM with fused RoPE/split/fp16 epilogue
    gemm_f16<<<dim3(24, 16), 256, SMEM_F>>>(xh, wth, nullptr, 3072, DM, 0,
                                            qh, kh, vh, cosT, sinT);

    attn<<<dim3(SEQ / QPB, NH), 256>>>(anchors);

    // out = att @ Wo (plain fp32 epilogue)
    gemm_f16<<<dim3(8, 16), 256, SMEM_F>>>(ath, woth, out, DM, DM, 1,
                                           nullptr, nullptr, nullptr, nullptr, nullptr);
}

// round 8
// speedup vs baseline: 5.7819x; 1.0742x over previous
#include <cuda_runtime.h>
#include <cuda_fp16.h>
#include <cstdint>

#define SEQ 2048
#define DM 1024
#define NH 16
#define HD 64
#define NANCH 3
#define QPB 4

// ---------------- scratch ------------------------------------------------------
__device__ __half g_qh16[SEQ * DM];          // Q after RoPE, fp16 [S, H*D]
__device__ __half g_khh[NH * SEQ * HD];      // K after RoPE, fp16 [H,S,D] (128B rows)
__device__ __half g_vhh[SEQ * DM];           // V fp16 [S, H*D]
__device__ __half g_xh[SEQ * DM];            // x fp16
__device__ __half g_wth[3072 * DM];          // [n,k] Wq|Wk|Wv^T fp16
__device__ __half g_woth[DM * DM];           // [n,k] Wo^T fp16
__device__ __half g_ath[SEQ * DM];           // attn out fp16 [S, H*D]

// ---------------- PTX helpers --------------------------------------------------
__device__ __forceinline__ uint32_t smem_u32(const void* p) {
    uint32_t a;
    asm("{ .reg .u64 t; cvta.to.shared.u64 t, %1; cvt.u32.u64 %0, t; }" : "=r"(a) : "l"(p));
    return a;
}
__device__ __forceinline__ void cp16(uint32_t s, const void* g) {
    asm volatile("cp.async.cg.shared.global [%0], [%1], 16;" :: "r"(s), "l"(g));
}
#define CP_COMMIT() asm volatile("cp.async.commit_group;" ::: "memory")
#define CP_WAIT1()  asm volatile("cp.async.wait_group 1;" ::: "memory")
#define CP_WAIT0()  asm volatile("cp.async.wait_group 0;" ::: "memory")

__device__ __forceinline__ void ldsm_x4(uint32_t& r0, uint32_t& r1, uint32_t& r2,
                                        uint32_t& r3, uint32_t a) {
    asm volatile("ldmatrix.sync.aligned.m8n8.x4.shared.b16 {%0,%1,%2,%3}, [%4];"
                 : "=r"(r0), "=r"(r1), "=r"(r2), "=r"(r3) : "r"(a));
}
__device__ __forceinline__ void mma_f16(float* d, const uint32_t* a, const uint32_t* b) {
    asm volatile(
        "mma.sync.aligned.m16n8k16.row.col.f32.f16.f16.f32 "
        "{%0,%1,%2,%3}, {%4,%5,%6,%7}, {%8,%9}, {%0,%1,%2,%3};"
        : "+f"(d[0]), "+f"(d[1]), "+f"(d[2]), "+f"(d[3])
        : "r"(a[0]), "r"(a[1]), "r"(a[2]), "r"(a[3]), "r"(b[0]), "r"(b[1]));
}

// ---------------- prep -----------------------------------------------------------
__global__ void split_x(const float* __restrict__ x) {
    int i = blockIdx.x * 256 + threadIdx.x;
    g_xh[i] = __float2half(x[i]);
}

// W [k][n] -> Wt [n][k] fp16. z 0..2 -> Wq/Wk/Wv; z==3 -> Wo
__global__ void transpose_w(const float* __restrict__ Wq, const float* __restrict__ Wk,
                            const float* __restrict__ Wv, const float* __restrict__ Wo) {
    __shared__ float tile[32][33];
    int z = blockIdx.z;
    const float* W = (z == 0) ? Wq : (z == 1) ? Wk : (z == 2) ? Wv : Wo;
    __half* dst = (z < 3) ? (g_wth + (size_t)z * DM * DM) : g_woth;
    int k0 = blockIdx.y * 32, n0 = blockIdx.x * 32;
    int tx = threadIdx.x, ty = threadIdx.y;
    tile[ty][tx] = W[(size_t)(k0 + ty) * DM + n0 + tx];
    __syncthreads();
    dst[(size_t)(n0 + ty) * DM + k0 + tx] = __float2half(tile[tx][ty]);
}

// ---------------- fp16 GEMM: C[M,N] = A[M,K] @ B[N,K]^T --------------------------
#define F_BK 64
#define F_STG 32768
#define F_OFF_B 16384
#define F_NSTAGE 3

__device__ __forceinline__ uint32_t swz8(uint32_t row, uint32_t seg) {
    return row * 128 + ((seg ^ (row & 7)) << 4);
}

__device__ __forceinline__ void f16_load_chunk(
    uint32_t stage, int tid, int c, int m0, int n0, int K,
    const __half* A, const __half* B)
{
    #pragma unroll
    for (int mtx = 0; mtx < 2; mtx++) {
        const int r0 = (mtx == 0) ? m0 : n0;
        const __half* src = (mtx == 0) ? A : B;
        const uint32_t off = mtx ? F_OFF_B : 0;
        #pragma unroll
        for (int i = 0; i < 4; i++) {
            int lin = i * 256 + tid;
            int row = lin >> 3, seg = lin & 7;
            const void* g = src + (size_t)(r0 + row) * K + c * F_BK + seg * 8;
            cp16(stage + off + swz8(row, seg), g);
        }
    }
}

__global__ void __launch_bounds__(256) gemm_f16(
    const __half* __restrict__ A, const __half* __restrict__ B,
    float* __restrict__ C, int Nstride, int K, int mode,
    __half* __restrict__ Qout, __half* __restrict__ Kout, __half* __restrict__ Vout,
    const float* __restrict__ cosT, const float* __restrict__ sinT)
{
    extern __shared__ __align__(1024) char dsm[];
    const uint32_t tiles = smem_u32(dsm);

    const int tid = threadIdx.x;
    const int m0 = blockIdx.y * 128, n0 = blockIdx.x * 128;
    const int nCh = K / F_BK;

    const int w = tid >> 5, lane = tid & 31;
    const int wm = (w & 3) * 32;
    const int wn = (w >> 2) * 64;

    float acc[2][8][4];
    #pragma unroll
    for (int i = 0; i < 2; i++)
        #pragma unroll
        for (int j = 0; j < 8; j++)
            #pragma unroll
            for (int e = 0; e < 4; e++) acc[i][j][e] = 0.f;

    f16_load_chunk(tiles, tid, 0, m0, n0, K, A, B); CP_COMMIT();
    f16_load_chunk(tiles + F_STG, tid, 1, m0, n0, K, A, B); CP_COMMIT();

    const int aRowL = lane & 15;
    const int aSegL = lane >> 4;
    const int bRowL = ((lane >> 4) & 1) * 8 + (lane & 7);
    const int bSegL = (lane >> 3) & 1;

    for (int c = 0; c < nCh; c++) {
        const uint32_t buf = tiles + (c % F_NSTAGE) * F_STG;
        CP_WAIT1();
        __syncthreads();
        if (c + 2 < nCh)
            f16_load_chunk(tiles + ((c + 2) % F_NSTAGE) * F_STG, tid, c + 2, m0, n0, K, A, B);
        CP_COMMIT();

        #pragma unroll
        for (int k16 = 0; k16 < 4; k16++) {
            uint32_t af[2][4], bf[4][4];
            #pragma unroll
            for (int mt = 0; mt < 2; mt++) {
                uint32_t row = wm + mt * 16 + aRowL;
                ldsm_x4(af[mt][0], af[mt][1], af[mt][2], af[mt][3],
                        buf + swz8(row, k16 * 2 + aSegL));
            }
            #pragma unroll
            for (int np = 0; np < 4; np++) {
                uint32_t row = wn + np * 16 + bRowL;
                ldsm_x4(bf[np][0], bf[np][1], bf[np][2], bf[np][3],
                        buf + F_OFF_B + swz8(row, k16 * 2 + bSegL));
            }
            #pragma unroll
            for (int mt = 0; mt < 2; mt++)
                #pragma unroll
                for (int np = 0; np < 4; np++)
                    #pragma unroll
                    for (int h = 0; h < 2; h++)
                        mma_f16(acc[mt][np * 2 + h], af[mt], &bf[np][h * 2]);
        }
        __syncthreads();
    }

    const int erow = lane >> 2, ecol = (lane & 3) * 2;

    if (mode == 0) {
        const int ncol = n0 + wn;
        const int zsel = ncol >> 10;
        const int hh = (ncol >> 6) & 15;
        #pragma unroll
        for (int mt = 0; mt < 2; mt++) {
            #pragma unroll
            for (int rsel = 0; rsel < 2; rsel++) {
                const int s = m0 + wm + mt * 16 + erow + rsel * 8;
                if (zsel == 2) {
                    __half* vb = Vout + (size_t)s * DM + hh * HD;
                    #pragma unroll
                    for (int nt = 0; nt < 8; nt++)
                        *(__half2*)(vb + nt * 8 + ecol) =
                            __floats2half2_rn(acc[mt][nt][rsel * 2], acc[mt][nt][rsel * 2 + 1]);
                } else {
                    __half* ob = (zsel == 0) ? (Qout + (size_t)s * DM + hh * HD)
                                             : (Kout + ((size_t)hh * SEQ + s) * HD);
                    #pragma unroll
                    for (int nt = 0; nt < 4; nt++) {
                        const int d0 = nt * 8 + ecol;
                        const float c0 = cosT[s * 32 + d0],     sn0 = sinT[s * 32 + d0];
                        const float c1 = cosT[s * 32 + d0 + 1], sn1 = sinT[s * 32 + d0 + 1];
                        const float a0 = acc[mt][nt][rsel * 2],     a1 = acc[mt][nt][rsel * 2 + 1];
                        const float b0 = acc[mt][nt + 4][rsel * 2], b1 = acc[mt][nt + 4][rsel * 2 + 1];
                        *(__half2*)(ob + d0) =
                            __floats2half2_rn(a0 * c0 - b0 * sn0, a1 * c1 - b1 * sn1);
                        *(__half2*)(ob + d0 + 32) =
                            __floats2half2_rn(b0 * c0 + a0 * sn0, b1 * c1 + a1 * sn1);
                    }
                }
            }
        }
    } else {
        #pragma unroll
        for (int mt = 0; mt < 2; mt++)
            #pragma unroll
            for (int nt = 0; nt < 8; nt++) {
                const float* d = acc[mt][nt];
                size_t r = (size_t)(m0 + wm + mt * 16 + erow);
                size_t col = n0 + wn + nt * 8 + ecol;
                *(float2*)&C[r * Nstride + col]       = make_float2(d[0], d[1]);
                *(float2*)&C[(r + 8) * Nstride + col] = make_float2(d[2], d[3]);
            }
    }
}

// ---------------- sparse attention: 4 queries / 256-thread block ----------------
// K tiles staged coalesced into smem via cp.async (16-row tiles are contiguous).
__global__ void __launch_bounds__(256) attn(const int* __restrict__ anchors) {
    const int h = blockIdx.y;
    const int tid = threadIdx.x;
    const int ql = tid >> 6;
    const int j = tid & 63;
    const int s = blockIdx.x * QPB + ql;

    __shared__ __align__(16) char sK[QPB][4 * 2048];   // 4 tiles x 16 rows x 128B
    __shared__ float sqf[QPB][64];
    __shared__ float swt[QPB][64];
    __shared__ int sidx[QPB][64];
    __shared__ int stile[QPB][4];
    __shared__ float wred[QPB][2][2];

    // q (RoPE'd fp16 -> fp32 smem) and tile indices
    sqf[ql][j] = __half2float(g_qh16[(size_t)s * DM + h * HD + j]);
    if (j < 4)
        stile[ql][j] = (j < NANCH) ? anchors[(h * SEQ + s) * NANCH + j] : (s >> 4);
    __syncthreads();

    // stage 4 K tiles (2KB each, contiguous in gmem) coalesced into smem
    {
        const uint32_t sbase = smem_u32(sK[ql]);
        #pragma unroll
        for (int i = 0; i < 8; i++) {
            const int chunk = i * 64 + j;          // 0..511
            const int tile = chunk >> 7;
            const int c = chunk & 127;             // 16B chunk within tile
            const int r = c >> 3, seg = c & 7;
            const char* g = (const char*)(g_khh + ((size_t)h * SEQ + stile[ql][tile] * 16) * HD)
                            + c * 16;
            cp16(sbase + tile * 2048 + r * 128 + ((seg ^ (r & 7)) << 4), g);
        }
    }
    CP_COMMIT();

    const int kidx = stile[ql][j >> 4] * 16 + (j & 15);
    const bool masked = kidx > s;
    sidx[ql][j] = kidx;

    CP_WAIT0();
    __syncthreads();

    // logit: thread j dots q against smem K row j
    float logit = -1e30f;
    if (!masked) {
        const char* rowb = sK[ql] + (j >> 4) * 2048 + (j & 15) * 128;
        const int rx = (j & 7);                    // swizzle key (row & 7)
        float acc = 0.f;
        #pragma unroll
        for (int seg = 0; seg < 8; seg++) {
            const uint4 raw = *(const uint4*)(rowb + ((seg ^ rx) << 4));
            const uint32_t* u = (const uint32_t*)&raw;
            #pragma unroll
            for (int e = 0; e < 4; e++) {
                const float2 kv = __half22float2(*(const __half2*)&u[e]);
                acc = fmaf(kv.x, sqf[ql][seg * 8 + e * 2], acc);
                acc = fmaf(kv.y, sqf[ql][seg * 8 + e * 2 + 1], acc);
            }
        }
        logit = acc * 0.125f;
    }

    const int wq = (tid >> 5) & 1, lane = tid & 31;
    float m = logit;
    #pragma unroll
    for (int off = 16; off; off >>= 1) m = fmaxf(m, __shfl_xor_sync(~0u, m, off));
    if (lane == 0) wred[ql][0][wq] = m;
    __syncthreads();
    m = fmaxf(wred[ql][0][0], wred[ql][0][1]);

    const float e = masked ? 0.f : __expf(logit - m);
    float ssum = e;
    #pragma unroll
    for (int off = 16; off; off >>= 1) ssum += __shfl_xor_sync(~0u, ssum, off);
    if (lane == 0) wred[ql][1][wq] = ssum;
    __syncthreads();
    ssum = wred[ql][1][0] + wred[ql][1][1];

    swt[ql][j] = e / ssum;
    __syncthreads();

    // output: thread j owns dim j; fp16 V gather (coalesced in j)
    const __half* vbase = g_vhh + h * HD + j;
    float acc = 0.f;
    #pragma unroll 16
    for (int jj = 0; jj < 64; jj++)
        acc = fmaf(swt[ql][jj], __half2float(vbase[(size_t)sidx[ql][jj] * DM]), acc);

    g_ath[(size_t)s * DM + h * HD + j] = __float2half(acc);
}

// ---------------- launch ---------------------------------------------------------
extern "C" void kernel_launch(void* const* d_in, const int* in_sizes, int n_in,
                              void* d_out, int out_size)
{
    const float* x    = (const float*)d_in[0];
    const float* Wq   = (const float*)d_in[1];
    const float* Wk   = (const float*)d_in[2];
    const float* Wv   = (const float*)d_in[3];
    const float* Wo   = (const float*)d_in[4];
    const float* cosT = (const float*)d_in[5];
    const float* sinT = (const float*)d_in[6];
    const int* anchors = (const int*)d_in[7];
    float* out = (float*)d_out;

    const int SMEM_F = F_NSTAGE * F_STG;   // 96 KB
    cudaFuncSetAttribute(gemm_f16, cudaFuncAttributeMaxDynamicSharedMemorySize, SMEM_F);

    __half *xh = nullptr, *wth = nullptr, *woth = nullptr, *ath = nullptr;
    __half *qh = nullptr, *kh = nullptr, *vh = nullptr;
    cudaGetSymbolAddress((void**)&xh, g_xh);
    cudaGetSymbolAddress((void**)&wth, g_wth);
    cudaGetSymbolAddress((void**)&woth, g_woth);
    cudaGetSymbolAddress((void**)&ath, g_ath);
    cudaGetSymbolAddress((void**)&qh, g_qh16);
    cudaGetSymbolAddress((void**)&kh, g_khh);
    cudaGetSymbolAddress((void**)&vh, g_vhh);

    split_x<<<(SEQ * DM) / 256, 256>>>(x);
    transpose_w<<<dim3(32, 32, 4), dim3(32, 32)>>>(Wq, Wk, Wv, Wo);

    // QKV GEMM with fused RoPE/split/fp16 epilogue
    gemm_f16<<<dim3(24, 16), 256, SMEM_F>>>(xh, wth, nullptr, 3072, DM, 0,
                                            qh, kh, vh, cosT, sinT);

    attn<<<dim3(SEQ / QPB, NH), 256>>>(anchors);

    // out = att @ Wo (plain fp32 epilogue)
    gemm_f16<<<dim3(8, 16), 256, SMEM_F>>>(ath, woth, out, DM, DM, 1,
                                           nullptr, nullptr, nullptr, nullptr, nullptr);
}

// round 9
// speedup vs baseline: 5.9081x; 1.0218x over previous
#include <cuda_runtime.h>
#include <cuda_fp16.h>
#include <cstdint>

#define SEQ 2048
#define DM 1024
#define NH 16
#define HD 64
#define NANCH 3
#define QPB 4

// ---------------- scratch ------------------------------------------------------
__device__ __half g_qh16[SEQ * DM];          // Q after RoPE, fp16 [S, H*D]
__device__ __half g_khh[NH * SEQ * HD];      // K after RoPE, fp16 [H,S,D] (128B rows)
__device__ __half g_vhh[SEQ * DM];           // V fp16 [S, H*D]
__device__ __half g_xh[SEQ * DM];            // x fp16
__device__ __half g_wth[3072 * DM];          // [n,k] Wq|Wk|Wv^T fp16
__device__ __half g_woth[DM * DM];           // [n,k] Wo^T fp16
__device__ __half g_ath[SEQ * DM];           // attn out fp16 [S, H*D]

// ---------------- PTX helpers --------------------------------------------------
__device__ __forceinline__ uint32_t smem_u32(const void* p) {
    uint32_t a;
    asm("{ .reg .u64 t; cvta.to.shared.u64 t, %1; cvt.u32.u64 %0, t; }" : "=r"(a) : "l"(p));
    return a;
}
__device__ __forceinline__ void cp16(uint32_t s, const void* g) {
    asm volatile("cp.async.cg.shared.global [%0], [%1], 16;" :: "r"(s), "l"(g));
}
#define CP_COMMIT() asm volatile("cp.async.commit_group;" ::: "memory")
#define CP_WAIT1()  asm volatile("cp.async.wait_group 1;" ::: "memory")
#define CP_WAIT0()  asm volatile("cp.async.wait_group 0;" ::: "memory")

__device__ __forceinline__ void ldsm_x4(uint32_t& r0, uint32_t& r1, uint32_t& r2,
                                        uint32_t& r3, uint32_t a) {
    asm volatile("ldmatrix.sync.aligned.m8n8.x4.shared.b16 {%0,%1,%2,%3}, [%4];"
                 : "=r"(r0), "=r"(r1), "=r"(r2), "=r"(r3) : "r"(a));
}
__device__ __forceinline__ void mma_f16(float* d, const uint32_t* a, const uint32_t* b) {
    asm volatile(
        "mma.sync.aligned.m16n8k16.row.col.f32.f16.f16.f32 "
        "{%0,%1,%2,%3}, {%4,%5,%6,%7}, {%8,%9}, {%0,%1,%2,%3};"
        : "+f"(d[0]), "+f"(d[1]), "+f"(d[2]), "+f"(d[3])
        : "r"(a[0]), "r"(a[1]), "r"(a[2]), "r"(a[3]), "r"(b[0]), "r"(b[1]));
}

// ---------------- prep -----------------------------------------------------------
__global__ void split_x(const float* __restrict__ x) {
    int i = blockIdx.x * 256 + threadIdx.x;
    g_xh[i] = __float2half(x[i]);
}

// W [k][n] -> Wt [n][k] fp16. z 0..2 -> Wq/Wk/Wv; z==3 -> Wo
__global__ void transpose_w(const float* __restrict__ Wq, const float* __restrict__ Wk,
                            const float* __restrict__ Wv, const float* __restrict__ Wo) {
    __shared__ float tile[32][33];
    int z = blockIdx.z;
    const float* W = (z == 0) ? Wq : (z == 1) ? Wk : (z == 2) ? Wv : Wo;
    __half* dst = (z < 3) ? (g_wth + (size_t)z * DM * DM) : g_woth;
    int k0 = blockIdx.y * 32, n0 = blockIdx.x * 32;
    int tx = threadIdx.x, ty = threadIdx.y;
    tile[ty][tx] = W[(size_t)(k0 + ty) * DM + n0 + tx];
    __syncthreads();
    dst[(size_t)(n0 + ty) * DM + k0 + tx] = __float2half(tile[tx][ty]);
}

// ---------------- fp16 GEMM: C[M,N] = A[M,K] @ B[N,K]^T --------------------------
#define F_BK 64
#define F_STG 32768
#define F_OFF_B 16384
#define F_NSTAGE 3

__device__ __forceinline__ uint32_t swz8(uint32_t row, uint32_t seg) {
    return row * 128 + ((seg ^ (row & 7)) << 4);
}

__device__ __forceinline__ void f16_load_chunk(
    uint32_t stage, int tid, int c, int m0, int n0, int K,
    const __half* A, const __half* B)
{
    #pragma unroll
    for (int mtx = 0; mtx < 2; mtx++) {
        const int r0 = (mtx == 0) ? m0 : n0;
        const __half* src = (mtx == 0) ? A : B;
        const uint32_t off = mtx ? F_OFF_B : 0;
        #pragma unroll
        for (int i = 0; i < 4; i++) {
            int lin = i * 256 + tid;
            int row = lin >> 3, seg = lin & 7;
            const void* g = src + (size_t)(r0 + row) * K + c * F_BK + seg * 8;
            cp16(stage + off + swz8(row, seg), g);
        }
    }
}

__global__ void __launch_bounds__(256) gemm_f16(
    const __half* __restrict__ A, const __half* __restrict__ B,
    float* __restrict__ C, int Nstride, int K, int mode,
    __half* __restrict__ Qout, __half* __restrict__ Kout, __half* __restrict__ Vout,
    const float* __restrict__ cosT, const float* __restrict__ sinT)
{
    extern __shared__ __align__(1024) char dsm[];
    const uint32_t tiles = smem_u32(dsm);

    const int tid = threadIdx.x;
    const int m0 = blockIdx.y * 128, n0 = blockIdx.x * 128;
    const int nCh = K / F_BK;

    const int w = tid >> 5, lane = tid & 31;
    const int wm = (w & 3) * 32;
    const int wn = (w >> 2) * 64;

    float acc[2][8][4];
    #pragma unroll
    for (int i = 0; i < 2; i++)
        #pragma unroll
        for (int j = 0; j < 8; j++)
            #pragma unroll
            for (int e = 0; e < 4; e++) acc[i][j][e] = 0.f;

    f16_load_chunk(tiles, tid, 0, m0, n0, K, A, B); CP_COMMIT();
    f16_load_chunk(tiles + F_STG, tid, 1, m0, n0, K, A, B); CP_COMMIT();

    const int aRowL = lane & 15;
    const int aSegL = lane >> 4;
    const int bRowL = ((lane >> 4) & 1) * 8 + (lane & 7);
    const int bSegL = (lane >> 3) & 1;

    for (int c = 0; c < nCh; c++) {
        const uint32_t buf = tiles + (c % F_NSTAGE) * F_STG;
        CP_WAIT1();
        __syncthreads();
        if (c + 2 < nCh)
            f16_load_chunk(tiles + ((c + 2) % F_NSTAGE) * F_STG, tid, c + 2, m0, n0, K, A, B);
        CP_COMMIT();

        #pragma unroll
        for (int k16 = 0; k16 < 4; k16++) {
            uint32_t af[2][4], bf[4][4];
            #pragma unroll
            for (int mt = 0; mt < 2; mt++) {
                uint32_t row = wm + mt * 16 + aRowL;
                ldsm_x4(af[mt][0], af[mt][1], af[mt][2], af[mt][3],
                        buf + swz8(row, k16 * 2 + aSegL));
            }
            #pragma unroll
            for (int np = 0; np < 4; np++) {
                uint32_t row = wn + np * 16 + bRowL;
                ldsm_x4(bf[np][0], bf[np][1], bf[np][2], bf[np][3],
                        buf + F_OFF_B + swz8(row, k16 * 2 + bSegL));
            }
            #pragma unroll
            for (int mt = 0; mt < 2; mt++)
                #pragma unroll
                for (int np = 0; np < 4; np++)
                    #pragma unroll
                    for (int h = 0; h < 2; h++)
                        mma_f16(acc[mt][np * 2 + h], af[mt], &bf[np][h * 2]);
        }
        __syncthreads();
    }

    const int erow = lane >> 2, ecol = (lane & 3) * 2;

    if (mode == 0) {
        const int ncol = n0 + wn;
        const int zsel = ncol >> 10;
        const int hh = (ncol >> 6) & 15;
        #pragma unroll
        for (int mt = 0; mt < 2; mt++) {
            #pragma unroll
            for (int rsel = 0; rsel < 2; rsel++) {
                const int s = m0 + wm + mt * 16 + erow + rsel * 8;
                if (zsel == 2) {
                    __half* vb = Vout + (size_t)s * DM + hh * HD;
                    #pragma unroll
                    for (int nt = 0; nt < 8; nt++)
                        *(__half2*)(vb + nt * 8 + ecol) =
                            __floats2half2_rn(acc[mt][nt][rsel * 2], acc[mt][nt][rsel * 2 + 1]);
                } else {
                    __half* ob = (zsel == 0) ? (Qout + (size_t)s * DM + hh * HD)
                                             : (Kout + ((size_t)hh * SEQ + s) * HD);
                    #pragma unroll
                    for (int nt = 0; nt < 4; nt++) {
                        const int d0 = nt * 8 + ecol;
                        const float c0 = cosT[s * 32 + d0],     sn0 = sinT[s * 32 + d0];
                        const float c1 = cosT[s * 32 + d0 + 1], sn1 = sinT[s * 32 + d0 + 1];
                        const float a0 = acc[mt][nt][rsel * 2],     a1 = acc[mt][nt][rsel * 2 + 1];
                        const float b0 = acc[mt][nt + 4][rsel * 2], b1 = acc[mt][nt + 4][rsel * 2 + 1];
                        *(__half2*)(ob + d0) =
                            __floats2half2_rn(a0 * c0 - b0 * sn0, a1 * c1 - b1 * sn1);
                        *(__half2*)(ob + d0 + 32) =
                            __floats2half2_rn(b0 * c0 + a0 * sn0, b1 * c1 + a1 * sn1);
                    }
                }
            }
        }
    } else {
        #pragma unroll
        for (int mt = 0; mt < 2; mt++)
            #pragma unroll
            for (int nt = 0; nt < 8; nt++) {
                const float* d = acc[mt][nt];
                size_t r = (size_t)(m0 + wm + mt * 16 + erow);
                size_t col = n0 + wn + nt * 8 + ecol;
                *(float2*)&C[r * Nstride + col]       = make_float2(d[0], d[1]);
                *(float2*)&C[(r + 8) * Nstride + col] = make_float2(d[2], d[3]);
            }
    }
}

// ---------------- sparse attention: 4 queries / 256-thread block ----------------
__global__ void __launch_bounds__(256) attn(const int* __restrict__ anchors) {
    const int h = blockIdx.y;
    const int tid = threadIdx.x;
    const int ql = tid >> 6;
    const int j = tid & 63;
    const int s = blockIdx.x * QPB + ql;
    const int wq = (tid >> 5) & 1;           // warp within query
    const int lane = tid & 31;

    __shared__ __align__(16) char sK[QPB][4 * 2048];   // 4 tiles x 16 rows x 128B
    __shared__ float sqf[QPB][64];
    __shared__ float swt[QPB][64];
    __shared__ int svoff[QPB][64];           // kidx * DM (premultiplied)
    __shared__ int stile[QPB][4];
    __shared__ float wred[QPB][2][2];
    __shared__ float spart[QPB][2][64];

    // q (RoPE'd fp16 -> fp32 smem) and tile indices
    sqf[ql][j] = __half2float(g_qh16[(size_t)s * DM + h * HD + j]);
    if (j < 4)
        stile[ql][j] = (j < NANCH) ? anchors[(h * SEQ + s) * NANCH + j] : (s >> 4);
    __syncthreads();

    // stage 4 K tiles (2KB each, contiguous in gmem) coalesced into smem
    {
        const uint32_t sbase = smem_u32(sK[ql]);
        #pragma unroll
        for (int i = 0; i < 8; i++) {
            const int chunk = i * 64 + j;          // 0..511
            const int tile = chunk >> 7;
            const int c = chunk & 127;             // 16B chunk within tile
            const int r = c >> 3, seg = c & 7;
            const char* g = (const char*)(g_khh + ((size_t)h * SEQ + stile[ql][tile] * 16) * HD)
                            + c * 16;
            cp16(sbase + tile * 2048 + r * 128 + ((seg ^ (r & 7)) << 4), g);
        }
    }
    CP_COMMIT();

    const int kidx = stile[ql][j >> 4] * 16 + (j & 15);
    const bool masked = kidx > s;
    svoff[ql][j] = kidx * DM;

    CP_WAIT0();
    __syncthreads();

    // logit: thread j dots q against smem K row j
    float logit = -1e30f;
    if (!masked) {
        const char* rowb = sK[ql] + (j >> 4) * 2048 + (j & 15) * 128;
        const int rx = (j & 7);
        float acc = 0.f;
        #pragma unroll
        for (int seg = 0; seg < 8; seg++) {
            const uint4 raw = *(const uint4*)(rowb + ((seg ^ rx) << 4));
            const uint32_t* u = (const uint32_t*)&raw;
            #pragma unroll
            for (int e = 0; e < 4; e++) {
                const float2 kv = __half22float2(*(const __half2*)&u[e]);
                acc = fmaf(kv.x, sqf[ql][seg * 8 + e * 2], acc);
                acc = fmaf(kv.y, sqf[ql][seg * 8 + e * 2 + 1], acc);
            }
        }
        logit = acc * 0.125f;
    }

    float m = logit;
    #pragma unroll
    for (int off = 16; off; off >>= 1) m = fmaxf(m, __shfl_xor_sync(~0u, m, off));
    if (lane == 0) wred[ql][0][wq] = m;
    __syncthreads();
    m = fmaxf(wred[ql][0][0], wred[ql][0][1]);

    const float e = masked ? 0.f : __expf(logit - m);
    float ssum = e;
    #pragma unroll
    for (int off = 16; off; off >>= 1) ssum += __shfl_xor_sync(~0u, ssum, off);
    if (lane == 0) wred[ql][1][wq] = ssum;
    __syncthreads();
    ssum = wred[ql][1][0] + wred[ql][1][1];

    swt[ql][j] = e / ssum;
    __syncthreads();

    // V phase: warp wq handles keys 32wq..32wq+31; lane owns dim pair (2l, 2l+1).
    // One half2 load per key = full 128B coalesced line per warp instruction.
    {
        const __half* vb = g_vhh + h * HD + 2 * lane;
        float ax = 0.f, ay = 0.f;
        const int kb = wq * 32;
        #pragma unroll
        for (int i = 0; i < 32; i++) {
            const float wgt = swt[ql][kb + i];
            const float2 vf = __half22float2(*(const __half2*)(vb + svoff[ql][kb + i]));
            ax = fmaf(wgt, vf.x, ax);
            ay = fmaf(wgt, vf.y, ay);
        }
        spart[ql][wq][2 * lane]     = ax;
        spart[ql][wq][2 * lane + 1] = ay;
    }
    __syncthreads();

    g_ath[(size_t)s * DM + h * HD + j] =
        __float2half(spart[ql][0][j] + spart[ql][1][j]);
}

// ---------------- launch ---------------------------------------------------------
extern "C" void kernel_launch(void* const* d_in, const int* in_sizes, int n_in,
                              void* d_out, int out_size)
{
    const float* x    = (const float*)d_in[0];
    const float* Wq   = (const float*)d_in[1];
    const float* Wk   = (const float*)d_in[2];
    const float* Wv   = (const float*)d_in[3];
    const float* Wo   = (const float*)d_in[4];
    const float* cosT = (const float*)d_in[5];
    const float* sinT = (const float*)d_in[6];
    const int* anchors = (const int*)d_in[7];
    float* out = (float*)d_out;

    const int SMEM_F = F_NSTAGE * F_STG;   // 96 KB
    cudaFuncSetAttribute(gemm_f16, cudaFuncAttributeMaxDynamicSharedMemorySize, SMEM_F);

    __half *xh = nullptr, *wth = nullptr, *woth = nullptr, *ath = nullptr;
    __half *qh = nullptr, *kh = nullptr, *vh = nullptr;
    cudaGetSymbolAddress((void**)&xh, g_xh);
    cudaGetSymbolAddress((void**)&wth, g_wth);
    cudaGetSymbolAddress((void**)&woth, g_woth);
    cudaGetSymbolAddress((void**)&ath, g_ath);
    cudaGetSymbolAddress((void**)&qh, g_qh16);
    cudaGetSymbolAddress((void**)&kh, g_khh);
    cudaGetSymbolAddress((void**)&vh, g_vhh);

    split_x<<<(SEQ * DM) / 256, 256>>>(x);
    transpose_w<<<dim3(32, 32, 4), dim3(32, 32)>>>(Wq, Wk, Wv, Wo);

    // QKV GEMM with fused RoPE/split/fp16 epilogue
    gemm_f16<<<dim3(24, 16), 256, SMEM_F>>>(xh, wth, nullptr, 3072, DM, 0,
                                            qh, kh, vh, cosT, sinT);

    attn<<<dim3(SEQ / QPB, NH), 256>>>(anchors);

    // out = att @ Wo (plain fp32 epilogue)
    gemm_f16<<<dim3(8, 16), 256, SMEM_F>>>(ath, woth, out, DM, DM, 1,
                                           nullptr, nullptr, nullptr, nullptr, nullptr);
}

// round 10
// speedup vs baseline: 6.0842x; 1.0298x over previous
#include <cuda_runtime.h>
#include <cuda_fp16.h>
#include <cstdint>

#define SEQ 2048
#define DM 1024
#define NH 16
#define HD 64
#define NANCH 3
#define QPB 4

// ---------------- scratch ------------------------------------------------------
__device__ __half g_qh16[SEQ * DM];          // Q after RoPE, fp16 [S, H*D]
__device__ __half g_khh[NH * SEQ * HD];      // K after RoPE, fp16 [H,S,D] (128B rows)
__device__ __half g_vhh[NH * SEQ * HD];      // V fp16 [H,S,D] (128B rows)
__device__ __half g_xh[SEQ * DM];            // x fp16
__device__ __half g_wth[3072 * DM];          // [n,k] Wq|Wk|Wv^T fp16
__device__ __half g_woth[DM * DM];           // [n,k] Wo^T fp16
__device__ __half g_ath[SEQ * DM];           // attn out fp16 [S, H*D]

// ---------------- PTX helpers --------------------------------------------------
__device__ __forceinline__ uint32_t smem_u32(const void* p) {
    uint32_t a;
    asm("{ .reg .u64 t; cvta.to.shared.u64 t, %1; cvt.u32.u64 %0, t; }" : "=r"(a) : "l"(p));
    return a;
}
__device__ __forceinline__ void cp16(uint32_t s, const void* g) {
    asm volatile("cp.async.cg.shared.global [%0], [%1], 16;" :: "r"(s), "l"(g));
}
#define CP_COMMIT() asm volatile("cp.async.commit_group;" ::: "memory")
#define CP_WAIT1()  asm volatile("cp.async.wait_group 1;" ::: "memory")
#define CP_WAIT0()  asm volatile("cp.async.wait_group 0;" ::: "memory")

__device__ __forceinline__ void ldsm_x4(uint32_t& r0, uint32_t& r1, uint32_t& r2,
                                        uint32_t& r3, uint32_t a) {
    asm volatile("ldmatrix.sync.aligned.m8n8.x4.shared.b16 {%0,%1,%2,%3}, [%4];"
                 : "=r"(r0), "=r"(r1), "=r"(r2), "=r"(r3) : "r"(a));
}
__device__ __forceinline__ void mma_f16(float* d, const uint32_t* a, const uint32_t* b) {
    asm volatile(
        "mma.sync.aligned.m16n8k16.row.col.f32.f16.f16.f32 "
        "{%0,%1,%2,%3}, {%4,%5,%6,%7}, {%8,%9}, {%0,%1,%2,%3};"
        : "+f"(d[0]), "+f"(d[1]), "+f"(d[2]), "+f"(d[3])
        : "r"(a[0]), "r"(a[1]), "r"(a[2]), "r"(a[3]), "r"(b[0]), "r"(b[1]));
}

// ---------------- prep -----------------------------------------------------------
__global__ void split_x(const float* __restrict__ x) {
    int i = blockIdx.x * 256 + threadIdx.x;
    g_xh[i] = __float2half(x[i]);
}

// W [k][n] -> Wt [n][k] fp16. z 0..2 -> Wq/Wk/Wv; z==3 -> Wo
__global__ void transpose_w(const float* __restrict__ Wq, const float* __restrict__ Wk,
                            const float* __restrict__ Wv, const float* __restrict__ Wo) {
    __shared__ float tile[32][33];
    int z = blockIdx.z;
    const float* W = (z == 0) ? Wq : (z == 1) ? Wk : (z == 2) ? Wv : Wo;
    __half* dst = (z < 3) ? (g_wth + (size_t)z * DM * DM) : g_woth;
    int k0 = blockIdx.y * 32, n0 = blockIdx.x * 32;
    int tx = threadIdx.x, ty = threadIdx.y;
    tile[ty][tx] = W[(size_t)(k0 + ty) * DM + n0 + tx];
    __syncthreads();
    dst[(size_t)(n0 + ty) * DM + k0 + tx] = __float2half(tile[tx][ty]);
}

// ---------------- fp16 GEMM: C[M,N] = A[M,K] @ B[N,K]^T --------------------------
#define F_BK 64
#define F_STG 32768
#define F_OFF_B 16384
#define F_NSTAGE 3

__device__ __forceinline__ uint32_t swz8(uint32_t row, uint32_t seg) {
    return row * 128 + ((seg ^ (row & 7)) << 4);
}

__device__ __forceinline__ void f16_load_chunk(
    uint32_t stage, int tid, int c, int m0, int n0, int K,
    const __half* A, const __half* B)
{
    #pragma unroll
    for (int mtx = 0; mtx < 2; mtx++) {
        const int r0 = (mtx == 0) ? m0 : n0;
        const __half* src = (mtx == 0) ? A : B;
        const uint32_t off = mtx ? F_OFF_B : 0;
        #pragma unroll
        for (int i = 0; i < 4; i++) {
            int lin = i * 256 + tid;
            int row = lin >> 3, seg = lin & 7;
            const void* g = src + (size_t)(r0 + row) * K + c * F_BK + seg * 8;
            cp16(stage + off + swz8(row, seg), g);
        }
    }
}

__global__ void __launch_bounds__(256) gemm_f16(
    const __half* __restrict__ A, const __half* __restrict__ B,
    float* __restrict__ C, int Nstride, int K, int mode,
    __half* __restrict__ Qout, __half* __restrict__ Kout, __half* __restrict__ Vout,
    const float* __restrict__ cosT, const float* __restrict__ sinT)
{
    extern __shared__ __align__(1024) char dsm[];
    const uint32_t tiles = smem_u32(dsm);

    const int tid = threadIdx.x;
    const int m0 = blockIdx.y * 128, n0 = blockIdx.x * 128;
    const int nCh = K / F_BK;

    const int w = tid >> 5, lane = tid & 31;
    const int wm = (w & 3) * 32;
    const int wn = (w >> 2) * 64;

    float acc[2][8][4];
    #pragma unroll
    for (int i = 0; i < 2; i++)
        #pragma unroll
        for (int j = 0; j < 8; j++)
            #pragma unroll
            for (int e = 0; e < 4; e++) acc[i][j][e] = 0.f;

    f16_load_chunk(tiles, tid, 0, m0, n0, K, A, B); CP_COMMIT();
    f16_load_chunk(tiles + F_STG, tid, 1, m0, n0, K, A, B); CP_COMMIT();

    const int aRowL = lane & 15;
    const int aSegL = lane >> 4;
    const int bRowL = ((lane >> 4) & 1) * 8 + (lane & 7);
    const int bSegL = (lane >> 3) & 1;

    for (int c = 0; c < nCh; c++) {
        const uint32_t buf = tiles + (c % F_NSTAGE) * F_STG;
        CP_WAIT1();
        __syncthreads();
        if (c + 2 < nCh)
            f16_load_chunk(tiles + ((c + 2) % F_NSTAGE) * F_STG, tid, c + 2, m0, n0, K, A, B);
        CP_COMMIT();

        #pragma unroll
        for (int k16 = 0; k16 < 4; k16++) {
            uint32_t af[2][4], bf[4][4];
            #pragma unroll
            for (int mt = 0; mt < 2; mt++) {
                uint32_t row = wm + mt * 16 + aRowL;
                ldsm_x4(af[mt][0], af[mt][1], af[mt][2], af[mt][3],
                        buf + swz8(row, k16 * 2 + aSegL));
            }
            #pragma unroll
            for (int np = 0; np < 4; np++) {
                uint32_t row = wn + np * 16 + bRowL;
                ldsm_x4(bf[np][0], bf[np][1], bf[np][2], bf[np][3],
                        buf + F_OFF_B + swz8(row, k16 * 2 + bSegL));
            }
            #pragma unroll
            for (int mt = 0; mt < 2; mt++)
                #pragma unroll
                for (int np = 0; np < 4; np++)
                    #pragma unroll
                    for (int h = 0; h < 2; h++)
                        mma_f16(acc[mt][np * 2 + h], af[mt], &bf[np][h * 2]);
        }
        __syncthreads();
    }

    const int erow = lane >> 2, ecol = (lane & 3) * 2;

    if (mode == 0) {
        const int ncol = n0 + wn;
        const int zsel = ncol >> 10;
        const int hh = (ncol >> 6) & 15;
        #pragma unroll
        for (int mt = 0; mt < 2; mt++) {
            #pragma unroll
            for (int rsel = 0; rsel < 2; rsel++) {
                const int s = m0 + wm + mt * 16 + erow + rsel * 8;
                if (zsel == 2) {
                    __half* vb = Vout + ((size_t)hh * SEQ + s) * HD;
                    #pragma unroll
                    for (int nt = 0; nt < 8; nt++)
                        *(__half2*)(vb + nt * 8 + ecol) =
                            __floats2half2_rn(acc[mt][nt][rsel * 2], acc[mt][nt][rsel * 2 + 1]);
                } else {
                    __half* ob = (zsel == 0) ? (Qout + (size_t)s * DM + hh * HD)
                                             : (Kout + ((size_t)hh * SEQ + s) * HD);
                    #pragma unroll
                    for (int nt = 0; nt < 4; nt++) {
                        const int d0 = nt * 8 + ecol;
                        const float c0 = cosT[s * 32 + d0],     sn0 = sinT[s * 32 + d0];
                        const float c1 = cosT[s * 32 + d0 + 1], sn1 = sinT[s * 32 + d0 + 1];
                        const float a0 = acc[mt][nt][rsel * 2],     a1 = acc[mt][nt][rsel * 2 + 1];
                        const float b0 = acc[mt][nt + 4][rsel * 2], b1 = acc[mt][nt + 4][rsel * 2 + 1];
                        *(__half2*)(ob + d0) =
                            __floats2half2_rn(a0 * c0 - b0 * sn0, a1 * c1 - b1 * sn1);
                        *(__half2*)(ob + d0 + 32) =
                            __floats2half2_rn(b0 * c0 + a0 * sn0, b1 * c1 + a1 * sn1);
                    }
                }
            }
        }
    } else {
        #pragma unroll
        for (int mt = 0; mt < 2; mt++)
            #pragma unroll
            for (int nt = 0; nt < 8; nt++) {
                const float* d = acc[mt][nt];
                size_t r = (size_t)(m0 + wm + mt * 16 + erow);
                size_t col = n0 + wn + nt * 8 + ecol;
                *(float2*)&C[r * Nstride + col]       = make_float2(d[0], d[1]);
                *(float2*)&C[(r + 8) * Nstride + col] = make_float2(d[2], d[3]);
            }
    }
}

// ---------------- sparse attention: 4 queries / 256-thread block ----------------
__global__ void __launch_bounds__(256) attn(const int* __restrict__ anchors) {
    const int h = blockIdx.y;
    const int tid = threadIdx.x;
    const int ql = tid >> 6;
    const int j = tid & 63;
    const int s = blockIdx.x * QPB + ql;
    const int wq = (tid >> 5) & 1;           // warp within query
    const int lane = tid & 31;

    __shared__ __align__(16) char sK[QPB][4 * 2048];   // 4 tiles x 16 rows x 128B
    __shared__ float sqf[QPB][64];
    __shared__ int stile[QPB][4];
    __shared__ float wred[QPB][2][2];
    __shared__ float spart[QPB][2][64];

    // q (RoPE'd fp16 -> fp32 smem) and tile indices
    sqf[ql][j] = __half2float(g_qh16[(size_t)s * DM + h * HD + j]);
    if (j < 4)
        stile[ql][j] = (j < NANCH) ? anchors[(h * SEQ + s) * NANCH + j] : (s >> 4);
    __syncthreads();

    // stage 4 K tiles (2KB each, contiguous in gmem) coalesced into smem
    {
        const uint32_t sbase = smem_u32(sK[ql]);
        #pragma unroll
        for (int i = 0; i < 8; i++) {
            const int chunk = i * 64 + j;          // 0..511
            const int tile = chunk >> 7;
            const int c = chunk & 127;             // 16B chunk within tile
            const int r = c >> 3, seg = c & 7;
            const char* g = (const char*)(g_khh + ((size_t)h * SEQ + stile[ql][tile] * 16) * HD)
                            + c * 16;
            cp16(sbase + tile * 2048 + r * 128 + ((seg ^ (r & 7)) << 4), g);
        }
    }
    CP_COMMIT();

    const int kidx = stile[ql][j >> 4] * 16 + (j & 15);
    const bool masked = kidx > s;
    const int mybo = kidx << 7;              // byte offset of V/K row in [H,S,D]

    CP_WAIT0();
    __syncthreads();

    // logit: thread j dots q against smem K row j
    float logit = -1e30f;
    if (!masked) {
        const char* rowb = sK[ql] + (j >> 4) * 2048 + (j & 15) * 128;
        const int rx = (j & 7);
        float acc = 0.f;
        #pragma unroll
        for (int seg = 0; seg < 8; seg++) {
            const uint4 raw = *(const uint4*)(rowb + ((seg ^ rx) << 4));
            const uint32_t* u = (const uint32_t*)&raw;
            #pragma unroll
            for (int e = 0; e < 4; e++) {
                const float2 kv = __half22float2(*(const __half2*)&u[e]);
                acc = fmaf(kv.x, sqf[ql][seg * 8 + e * 2], acc);
                acc = fmaf(kv.y, sqf[ql][seg * 8 + e * 2 + 1], acc);
            }
        }
        logit = acc * 0.125f;
    }

    float m = logit;
    #pragma unroll
    for (int off = 16; off; off >>= 1) m = fmaxf(m, __shfl_xor_sync(~0u, m, off));
    if (lane == 0) wred[ql][0][wq] = m;
    __syncthreads();
    m = fmaxf(wred[ql][0][0], wred[ql][0][1]);

    const float e = masked ? 0.f : __expf(logit - m);
    float ssum = e;
    #pragma unroll
    for (int off = 16; off; off >>= 1) ssum += __shfl_xor_sync(~0u, ssum, off);
    if (lane == 0) wred[ql][1][wq] = ssum;
    __syncthreads();
    ssum = wred[ql][1][0] + wred[ql][1][1];

    const float myw = e / ssum;              // weight of key j, held in register

    // V phase: warp wq covers its own 32 keys (weights/offsets via shuffle);
    // lane owns dim pair (2l, 2l+1): one half2 per key = full 128B line per warp.
    {
        const char* vb = (const char*)g_vhh + (size_t)h * SEQ * 128 + 4 * lane;
        float ax = 0.f, ay = 0.f;
        #pragma unroll
        for (int i = 0; i < 32; i++) {
            const float wgt = __shfl_sync(~0u, myw, i);
            const int boff  = __shfl_sync(~0u, mybo, i);
            const float2 vf = __half22float2(*(const __half2*)(vb + boff));
            ax = fmaf(wgt, vf.x, ax);
            ay = fmaf(wgt, vf.y, ay);
        }
        spart[ql][wq][2 * lane]     = ax;
        spart[ql][wq][2 * lane + 1] = ay;
    }
    __syncthreads();

    g_ath[(size_t)s * DM + h * HD + j] =
        __float2half(spart[ql][0][j] + spart[ql][1][j]);
}

// ---------------- launch ---------------------------------------------------------
extern "C" void kernel_launch(void* const* d_in, const int* in_sizes, int n_in,
                              void* d_out, int out_size)
{
    const float* x    = (const float*)d_in[0];
    const float* Wq   = (const float*)d_in[1];
    const float* Wk   = (const float*)d_in[2];
    const float* Wv   = (const float*)d_in[3];
    const float* Wo   = (const float*)d_in[4];
    const float* cosT = (const float*)d_in[5];
    const float* sinT = (const float*)d_in[6];
    const int* anchors = (const int*)d_in[7];
    float* out = (float*)d_out;

    const int SMEM_F = F_NSTAGE * F_STG;   // 96 KB
    cudaFuncSetAttribute(gemm_f16, cudaFuncAttributeMaxDynamicSharedMemorySize, SMEM_F);

    __half *xh = nullptr, *wth = nullptr, *woth = nullptr, *ath = nullptr;
    __half *qh = nullptr, *kh = nullptr, *vh = nullptr;
    cudaGetSymbolAddress((void**)&xh, g_xh);
    cudaGetSymbolAddress((void**)&wth, g_wth);
    cudaGetSymbolAddress((void**)&woth, g_woth);
    cudaGetSymbolAddress((void**)&ath, g_ath);
    cudaGetSymbolAddress((void**)&qh, g_qh16);
    cudaGetSymbolAddress((void**)&kh, g_khh);
    cudaGetSymbolAddress((void**)&vh, g_vhh);

    split_x<<<(SEQ * DM) / 256, 256>>>(x);
    transpose_w<<<dim3(32, 32, 4), dim3(32, 32)>>>(Wq, Wk, Wv, Wo);

    // QKV GEMM with fused RoPE/split/fp16 epilogue
    gemm_f16<<<dim3(24, 16), 256, SMEM_F>>>(xh, wth, nullptr, 3072, DM, 0,
                                            qh, kh, vh, cosT, sinT);

    attn<<<dim3(SEQ / QPB, NH), 256>>>(anchors);

    // out = att @ Wo (plain fp32 epilogue)
    gemm_f16<<<dim3(8, 16), 256, SMEM_F>>>(ath, woth, out, DM, DM, 1,
                                           nullptr, nullptr, nullptr, nullptr, nullptr);
}